// round 2
// baseline (speedup 1.0000x reference)
#include <cuda_runtime.h>
#include <cuda_bf16.h>
#include <cstdint>

#define Bb   256
#define Dd   256
#define Vv   2000
#define VTt  10000
#define OPTo 16
#define SEQs 10
#define SRCs 40
#define G3   768

// output layout (flattened tuple, float32)
#define OFF_LHS  0
#define OFF_MASK 256
#define OFF_GG   512
#define OFF_OPT  164352
#define OFF_TOPO 168448
#define OFF_EX   178688

// ---------------- device scratch ----------------
__device__ float d_gh[Bb*G3];
__device__ float d_gx[Bb*G3];
__device__ float d_ts[Bb*Dd];
__device__ float d_cat[Bb*2*Dd];
__device__ float d_soa[Bb*Dd];
__device__ float d_clog[SEQs*Bb*Vv];
__device__ float d_lse[SEQs*Bb];
__device__ int   d_inp[Bb];
__device__ unsigned char d_w[SEQs*Bb*Vv];
__device__ int   d_best[Bb];
__device__ int   d_sym[Bb*SEQs];
__device__ __nv_bfloat16 d_Ahi[Bb*SEQs*2*Dd];
__device__ __nv_bfloat16 d_Alo[Bb*SEQs*2*Dd];
__device__ __nv_bfloat16 d_WhiT[(size_t)VTt*2*Dd];
__device__ __nv_bfloat16 d_WloT[(size_t)VTt*2*Dd];

// ---------------- init ----------------
__global__ void k_init(const int* __restrict__ lhs, const float* __restrict__ ts0) {
    int i = blockIdx.x*blockDim.x + threadIdx.x;
    if (i < Bb) d_inp[i] = lhs[i];
    if (i < Bb*Dd) d_ts[i] = ts0[i];
}

// ---------------- copy small outputs ----------------
__global__ void k_copy(const int* __restrict__ lhs, const int* __restrict__ lmask,
                       const int* __restrict__ gg, float* __restrict__ out) {
    for (int i = blockIdx.x*blockDim.x + threadIdx.x; i < OFF_OPT; i += gridDim.x*blockDim.x) {
        if (i < 256)       out[i] = (float)lhs[i];
        else if (i < 512)  out[i] = (float)lmask[i-256];
        else               out[i] = (float)gg[i-512];
    }
}

// ---------------- generic fp32 SGEMM: C(M,N) = A(M,K)@B(K,N) + bias ----------------
// optional row gather on A (arows). 64x64 tile, BK=16, 256 threads, 4x4 per thread.
__global__ void sgemm64(const float* __restrict__ A, const float* __restrict__ Bm,
                        const float* __restrict__ bias, float* __restrict__ C,
                        int M, int N, int K, const int* __restrict__ arows) {
    __shared__ float As[64][17];
    __shared__ float Bs[16][65];
    int tid = threadIdx.x;
    int tx = tid & 15, ty = tid >> 4;
    int m0 = blockIdx.y*64, n0 = blockIdx.x*64;
    float acc[4][4];
    #pragma unroll
    for (int i=0;i<4;i++) {
        #pragma unroll
        for (int j=0;j<4;j++) acc[i][j]=0.f;
    }
    for (int k0 = 0; k0 < K; k0 += 16) {
        #pragma unroll
        for (int i = 0; i < 4; i++) {
            int idx = tid + i*256;
            int r = idx >> 4, c = idx & 15;
            int gr = m0 + r;
            float v = 0.f;
            if (gr < M) {
                int pr = arows ? arows[gr] : gr;
                v = A[(size_t)pr*K + k0 + c];
            }
            As[r][c] = v;
        }
        #pragma unroll
        for (int i = 0; i < 4; i++) {
            int idx = tid + i*256;
            int r = idx >> 6, c = idx & 63;
            int gc = n0 + c;
            float v = 0.f;
            if (gc < N) v = Bm[(size_t)(k0+r)*N + gc];
            Bs[r][c] = v;
        }
        __syncthreads();
        #pragma unroll
        for (int kk = 0; kk < 16; kk++) {
            float a[4], b[4];
            #pragma unroll
            for (int i=0;i<4;i++) a[i] = As[ty*4+i][kk];
            #pragma unroll
            for (int j=0;j<4;j++) b[j] = Bs[kk][tx*4+j];
            #pragma unroll
            for (int i=0;i<4;i++) {
                #pragma unroll
                for (int j=0;j<4;j++) acc[i][j] += a[i]*b[j];
            }
        }
        __syncthreads();
    }
    #pragma unroll
    for (int i=0;i<4;i++) {
        int r = m0 + ty*4 + i;
        if (r >= M) continue;
        #pragma unroll
        for (int j=0;j<4;j++) {
            int c = n0 + tx*4 + j;
            if (c < N) C[(size_t)r*N + c] = acc[i][j] + bias[c];
        }
    }
}

// ---------------- GRU gates + attention + concat ----------------
__global__ void k_gru(const float* __restrict__ ts0, const float* __restrict__ mem) {
    int b = blockIdx.x, j = threadIdx.x;
    __shared__ float hs[Dd];
    __shared__ float att[SRCs];
    float xr = d_gx[b*G3 + j], xz = d_gx[b*G3 + Dd + j], xn = d_gx[b*G3 + 2*Dd + j];
    float hr = d_gh[b*G3 + j], hz = d_gh[b*G3 + Dd + j], hn = d_gh[b*G3 + 2*Dd + j];
    float r = 1.f/(1.f + expf(-(xr+hr)));
    float z = 1.f/(1.f + expf(-(xz+hz)));
    float n = tanhf(xn + r*hn);
    float h = (1.f - z)*n + z*ts0[b*Dd + j];
    hs[j] = h;
    __syncthreads();
    int lane = j & 31, warp = j >> 5;
    for (int s = warp; s < SRCs; s += 8) {
        const float* mrow = mem + ((size_t)b*SRCs + s)*Dd;
        float sum = 0.f;
        for (int k = lane; k < Dd; k += 32) sum += hs[k]*mrow[k];
        #pragma unroll
        for (int o=16;o;o>>=1) sum += __shfl_down_sync(0xffffffffu, sum, o);
        if (lane == 0) att[s] = sum;
    }
    __syncthreads();
    if (j == 0) {
        float m = att[0];
        for (int s=1;s<SRCs;s++) m = fmaxf(m, att[s]);
        float ss = 0.f;
        for (int s=0;s<SRCs;s++){ att[s] = expf(att[s]-m); ss += att[s]; }
        float inv = 1.f/ss;
        for (int s=0;s<SRCs;s++) att[s] *= inv;
    }
    __syncthreads();
    float ctx = 0.f;
    for (int s=0;s<SRCs;s++) ctx += att[s]*mem[((size_t)b*SRCs+s)*Dd + j];
    d_cat[b*2*Dd + j]      = ctx;
    d_cat[b*2*Dd + Dd + j] = h;
}

// ---------------- tanh(soa), ts update ----------------
__global__ void k_ts() {
    int i = blockIdx.x*blockDim.x + threadIdx.x;  // B*D
    float s = tanhf(d_soa[i]);
    d_soa[i] = s;
    d_ts[i] = tanhf(d_ts[i] + s);
}

// ---------------- grammar w masks (all steps) ----------------
__global__ void k_w(const int* __restrict__ gg) {
    int tb = blockIdx.x;            // t*B + b
    int t = tb / Bb, b = tb % Bb;
    int tid = threadIdx.x;          // 64 threads
    __shared__ unsigned char ws[Vv];
    __shared__ int f0;
    for (int v = tid; v < Vv; v += 64) ws[v] = 0;
    if (tid == 0) f0 = 0;
    __syncthreads();
    if (tid < OPTo) {
        int base = ((b*OPTo + tid)*4)*SEQs + t;
        int sym = gg[base];
        int m   = gg[base + 3*SEQs];
        if (m) { if (sym > 0) ws[sym] = 1; else f0 = 1; }
    }
    __syncthreads();
    if (tid == 0) ws[0] = (unsigned char)f0;
    __syncthreads();
    unsigned char* outp = d_w + (size_t)tb*Vv;
    for (int v = tid; v < Vv; v += 64) outp[v] = ws[v];
}

// ---------------- apply mask + argmax -> next input ----------------
__global__ void k_mask(int t) {
    int b = blockIdx.x, tid = threadIdx.x;
    float* row = d_clog + ((size_t)t*Bb + b)*Vv;
    const unsigned char* wr = d_w + ((size_t)t*Bb + b)*Vv;
    const float LT = logf(1e-13f);
    float bv = -1e30f; int bi = Vv;
    for (int v = tid; v < Vv; v += 256) {
        float c = row[v];
        if (!wr[v]) c += LT;
        row[v] = c;
        if (c > bv) { bv = c; bi = v; }
    }
    __shared__ float sv[256]; __shared__ int si[256];
    sv[tid] = bv; si[tid] = bi;
    __syncthreads();
    for (int off = 128; off; off >>= 1) {
        if (tid < off) {
            if (sv[tid+off] > sv[tid] || (sv[tid+off] == sv[tid] && si[tid+off] < si[tid])) {
                sv[tid] = sv[tid+off]; si[tid] = si[tid+off];
            }
        }
        __syncthreads();
    }
    if (tid == 0) d_inp[b] = si[0];
}

// ---------------- logsumexp per (t,b) ----------------
__global__ void k_lse() {
    int tb = blockIdx.x, tid = threadIdx.x;
    const float* row = d_clog + (size_t)tb*Vv;
    __shared__ float sm[256];
    float m = -1e30f;
    for (int v = tid; v < Vv; v += 256) m = fmaxf(m, row[v]);
    sm[tid] = m; __syncthreads();
    for (int off=128;off;off>>=1){ if (tid<off) sm[tid]=fmaxf(sm[tid],sm[tid+off]); __syncthreads(); }
    float M = sm[0]; __syncthreads();
    float s = 0.f;
    for (int v = tid; v < Vv; v += 256) s += expf(row[v]-M);
    sm[tid] = s; __syncthreads();
    for (int off=128;off;off>>=1){ if (tid<off) sm[tid]+=sm[tid+off]; __syncthreads(); }
    if (tid == 0) d_lse[tb] = M + logf(sm[0]);
}

// ---------------- opts_logp, best, topo outputs ----------------
__global__ void k_opts(const int* __restrict__ gg, float* __restrict__ out) {
    int b = blockIdx.x, tid = threadIdx.x;
    __shared__ float vals[OPTo*SEQs];
    __shared__ float sol[OPTo];
    __shared__ int sbest;
    if (tid < OPTo*SEQs) {
        int o = tid / SEQs, t = tid % SEQs;
        int base = ((b*OPTo + o)*4)*SEQs + t;
        int m = gg[base + 3*SEQs];
        float v = 0.f;
        if (m) {
            int sym = gg[base];
            float lp = logf(expf(d_clog[((size_t)t*Bb + b)*Vv + sym] - d_lse[t*Bb + b]) + 1e-13f);
            v = lp;
        }
        vals[tid] = v;
    }
    __syncthreads();
    if (tid < OPTo) {
        float s = 0.f;
        #pragma unroll
        for (int t=0;t<SEQs;t++) s += vals[tid*SEQs + t];
        sol[tid] = s;
        out[OFF_OPT + b*OPTo + tid] = s;
    }
    __syncthreads();
    if (tid == 0) {
        int bi = 0; float bv = sol[0];
        for (int o=1;o<OPTo;o++) if (sol[o] > bv) { bv = sol[o]; bi = o; }
        sbest = bi; d_best[b] = bi;
    }
    __syncthreads();
    if (tid < 4*SEQs) {
        int c = tid / SEQs, s = tid % SEQs;
        int val = gg[((b*OPTo + sbest)*4 + c)*SEQs + s];
        out[OFF_TOPO + c*(Bb*SEQs) + b*SEQs + s] = (float)val;
        if (c == 0) d_sym[b*SEQs + s] = val;
    }
}

// ---------------- prep A (proj rows) hi/lo bf16 ----------------
__global__ void k_prepA(const float* __restrict__ emb) {
    int idx = blockIdx.x*blockDim.x + threadIdx.x;   // 2560*512 total
    int r = idx >> 9, k = idx & 511;
    int b = r / SEQs;
    float v = (k < Dd) ? emb[(size_t)d_sym[r]*Dd + k] : d_ts[b*Dd + (k - Dd)];
    __nv_bfloat16 h = __float2bfloat16(v);
    d_Ahi[idx] = h;
    d_Alo[idx] = __float2bfloat16(v - __bfloat162float(h));
}

// ---------------- prep W: transpose to (VT,512) + hi/lo bf16 ----------------
__global__ void k_prepW(const float* __restrict__ Wtok) {
    __shared__ float tile[32][33];
    int n0 = blockIdx.x*32, k0 = blockIdx.y*32;
    int tx = threadIdx.x, ty = threadIdx.y;   // 32x8
    #pragma unroll
    for (int i=0;i<4;i++) {
        int k = k0 + ty + i*8, n = n0 + tx;
        tile[ty+i*8][tx] = (n < VTt) ? Wtok[(size_t)k*VTt + n] : 0.f;
    }
    __syncthreads();
    #pragma unroll
    for (int i=0;i<4;i++) {
        int n = n0 + ty + i*8, k = k0 + tx;
        if (n < VTt) {
            float v = tile[tx][ty+i*8];
            __nv_bfloat16 h = __float2bfloat16(v);
            d_WhiT[(size_t)n*512 + k] = h;
            d_WloT[(size_t)n*512 + k] = __float2bfloat16(v - __bfloat162float(h));
        }
    }
}

// ---------------- exact_logit GEMM: bf16 split mma, 128x128x32 tiles ----------------
#define MMA16816(d, a, b) asm volatile( \
    "mma.sync.aligned.m16n8k16.row.col.f32.bf16.bf16.f32 " \
    "{%0,%1,%2,%3}, {%4,%5,%6,%7}, {%8,%9}, {%0,%1,%2,%3};\n" \
    : "+f"(d[0]), "+f"(d[1]), "+f"(d[2]), "+f"(d[3]) \
    : "r"(a[0]), "r"(a[1]), "r"(a[2]), "r"(a[3]), "r"(b[0]), "r"(b[1]))

#define ASTR 40  // smem stride in halves (conflict-free for frag loads)

__global__ __launch_bounds__(256) void k_exact(const float* __restrict__ btok,
                                               const float* __restrict__ tok,
                                               float* __restrict__ out) {
    __shared__ __nv_bfloat16 sAh[128*ASTR], sAl[128*ASTR], sBh[128*ASTR], sBl[128*ASTR];
    int tid = threadIdx.x;
    int m0 = blockIdx.y*128, n0 = blockIdx.x*128;
    int lane = tid & 31, warp = tid >> 5;
    int wm = warp >> 2, wn = warp & 3;        // 2x4 warps, warp tile 64x32
    int g = lane >> 2, tq = lane & 3;
    float acc[4][4][4];
    #pragma unroll
    for (int i=0;i<4;i++) {
        #pragma unroll
        for (int j=0;j<4;j++) {
            #pragma unroll
            for (int q=0;q<4;q++) acc[i][j][q] = 0.f;
        }
    }

    int row = tid >> 1;
    int kh  = (tid & 1) << 4;

    for (int k0 = 0; k0 < 512; k0 += 32) {
        // A tiles: rows m0..m0+127, k k0..k0+31 (always in-bounds, M=2560)
        {
            const uint4* p = (const uint4*)(d_Ahi + (size_t)(m0+row)*512 + k0 + kh);
            *(uint4*)&sAh[row*ASTR + kh]     = p[0];
            *(uint4*)&sAh[row*ASTR + kh + 8] = p[1];
            const uint4* q = (const uint4*)(d_Alo + (size_t)(m0+row)*512 + k0 + kh);
            *(uint4*)&sAl[row*ASTR + kh]     = q[0];
            *(uint4*)&sAl[row*ASTR + kh + 8] = q[1];
        }
        // B tiles (transposed weights, rows = n): guard n
        {
            int nr = n0 + row;
            uint4 z0 = make_uint4(0,0,0,0);
            uint4 h0 = z0, h1 = z0, l0 = z0, l1 = z0;
            if (nr < VTt) {
                const uint4* p = (const uint4*)(d_WhiT + (size_t)nr*512 + k0 + kh);
                h0 = p[0]; h1 = p[1];
                const uint4* q = (const uint4*)(d_WloT + (size_t)nr*512 + k0 + kh);
                l0 = q[0]; l1 = q[1];
            }
            *(uint4*)&sBh[row*ASTR + kh]     = h0;
            *(uint4*)&sBh[row*ASTR + kh + 8] = h1;
            *(uint4*)&sBl[row*ASTR + kh]     = l0;
            *(uint4*)&sBl[row*ASTR + kh + 8] = l1;
        }
        __syncthreads();
        #pragma unroll
        for (int ks = 0; ks < 2; ks++) {
            int kb = ks*16;
            uint32_t ah[4][4], al[4][4];
            #pragma unroll
            for (int mi=0;mi<4;mi++) {
                int rb = wm*64 + mi*16;
                int c0 = kb + tq*2;
                ah[mi][0] = *(const uint32_t*)&sAh[(rb+g)*ASTR + c0];
                ah[mi][1] = *(const uint32_t*)&sAh[(rb+g+8)*ASTR + c0];
                ah[mi][2] = *(const uint32_t*)&sAh[(rb+g)*ASTR + c0 + 8];
                ah[mi][3] = *(const uint32_t*)&sAh[(rb+g+8)*ASTR + c0 + 8];
                al[mi][0] = *(const uint32_t*)&sAl[(rb+g)*ASTR + c0];
                al[mi][1] = *(const uint32_t*)&sAl[(rb+g+8)*ASTR + c0];
                al[mi][2] = *(const uint32_t*)&sAl[(rb+g)*ASTR + c0 + 8];
                al[mi][3] = *(const uint32_t*)&sAl[(rb+g+8)*ASTR + c0 + 8];
            }
            uint32_t bh[4][2], bl[4][2];
            #pragma unroll
            for (int ni=0;ni<4;ni++) {
                int nb = wn*32 + ni*8 + g;
                bh[ni][0] = *(const uint32_t*)&sBh[nb*ASTR + kb + tq*2];
                bh[ni][1] = *(const uint32_t*)&sBh[nb*ASTR + kb + tq*2 + 8];
                bl[ni][0] = *(const uint32_t*)&sBl[nb*ASTR + kb + tq*2];
                bl[ni][1] = *(const uint32_t*)&sBl[nb*ASTR + kb + tq*2 + 8];
            }
            #pragma unroll
            for (int mi=0;mi<4;mi++) {
                #pragma unroll
                for (int ni=0;ni<4;ni++) {
                    MMA16816(acc[mi][ni], ah[mi], bh[ni]);
                    MMA16816(acc[mi][ni], ah[mi], bl[ni]);
                    MMA16816(acc[mi][ni], al[mi], bh[ni]);
                }
            }
        }
        __syncthreads();
    }
    const float LT = logf(1e-13f);
    #pragma unroll
    for (int mi=0;mi<4;mi++) {
        int r0 = m0 + wm*64 + mi*16 + g;
        int s0 = d_sym[r0];
        int s1 = d_sym[r0 + 8];
        #pragma unroll
        for (int ni=0;ni<4;ni++) {
            int c0 = n0 + wn*32 + ni*8 + tq*2;
            if (c0 < VTt) {
                float b0 = btok[c0];
                out[OFF_EX + (size_t)r0*VTt + c0]     = acc[mi][ni][0] + b0 + (tok[(size_t)s0*VTt + c0] > 0.f ? 0.f : LT);
                out[OFF_EX + (size_t)(r0+8)*VTt + c0] = acc[mi][ni][2] + b0 + (tok[(size_t)s1*VTt + c0] > 0.f ? 0.f : LT);
            }
            if (c0 + 1 < VTt) {
                float b1 = btok[c0+1];
                out[OFF_EX + (size_t)r0*VTt + c0+1]     = acc[mi][ni][1] + b1 + (tok[(size_t)s0*VTt + c0+1] > 0.f ? 0.f : LT);
                out[OFF_EX + (size_t)(r0+8)*VTt + c0+1] = acc[mi][ni][3] + b1 + (tok[(size_t)s1*VTt + c0+1] > 0.f ? 0.f : LT);
            }
        }
    }
}

// ---------------- host launcher ----------------
extern "C" void kernel_launch(void* const* d_in, const int* in_sizes, int n_in,
                              void* d_out, int out_size) {
    const int*   lhs   = (const int*)d_in[0];
    const int*   lmask = (const int*)d_in[1];
    const float* ts0   = (const float*)d_in[2];
    const int*   gg    = (const int*)d_in[3];
    const float* emb   = (const float*)d_in[4];
    const float* mem   = (const float*)d_in[5];
    const float* Wx    = (const float*)d_in[6];
    const float* Wh    = (const float*)d_in[7];
    const float* bx    = (const float*)d_in[8];
    const float* bh    = (const float*)d_in[9];
    const float* Wc    = (const float*)d_in[10];
    const float* bc    = (const float*)d_in[11];
    const float* Wsym  = (const float*)d_in[12];
    const float* bsym  = (const float*)d_in[13];
    const float* Wtok  = (const float*)d_in[14];
    const float* btok  = (const float*)d_in[15];
    const float* tok   = (const float*)d_in[16];
    float* out = (float*)d_out;

    void* pv;
    cudaGetSymbolAddress(&pv, d_gh);   float* p_gh   = (float*)pv;
    cudaGetSymbolAddress(&pv, d_gx);   float* p_gx   = (float*)pv;
    cudaGetSymbolAddress(&pv, d_cat);  float* p_cat  = (float*)pv;
    cudaGetSymbolAddress(&pv, d_soa);  float* p_soa  = (float*)pv;
    cudaGetSymbolAddress(&pv, d_clog); float* p_clog = (float*)pv;
    cudaGetSymbolAddress(&pv, d_inp);  int*   p_inp  = (int*)pv;

    k_init<<<256, 256>>>(lhs, ts0);
    // gh = tree_state @ Wh + bh  (constant across steps!)
    sgemm64<<<dim3(12,4), 256>>>(ts0, Wh, bh, p_gh, Bb, G3, Dd, nullptr);
    k_w<<<SEQs*Bb, 64>>>(gg);
    k_copy<<<642, 256>>>(lhs, lmask, gg, out);
    k_prepW<<<dim3((VTt+31)/32, 16), dim3(32,8)>>>(Wtok);

    for (int t = 0; t < SEQs; t++) {
        // gx = emb[inp] @ Wx + bx
        sgemm64<<<dim3(12,4), 256>>>(emb, Wx, bx, p_gx, Bb, G3, Dd, p_inp);
        k_gru<<<Bb, 256>>>(ts0, mem);
        // soa_raw = cat @ Wc + bc
        sgemm64<<<dim3(4,4), 256>>>(p_cat, Wc, bc, p_soa, Bb, Dd, 2*Dd, nullptr);
        k_ts<<<Bb, 256>>>();
        // logits = soa @ Wsym + bsym
        sgemm64<<<dim3(32,4), 256>>>(p_soa, Wsym, bsym, p_clog + (size_t)t*Bb*Vv,
                                     Bb, Vv, Dd, nullptr);
        k_mask<<<Bb, 256>>>(t);
    }

    k_lse<<<SEQs*Bb, 256>>>();
    k_opts<<<Bb, 256>>>(gg, out);
    k_prepA<<<(Bb*SEQs*2*Dd)/256, 256>>>(emb);
    k_exact<<<dim3((VTt+127)/128, (Bb*SEQs)/128), 256>>>(btok, tok, out);
}

// round 3
// speedup vs baseline: 1.0146x; 1.0146x over previous
#include <cuda_runtime.h>
#include <cuda_bf16.h>
#include <cstdint>

#define Bb   256
#define Dd   256
#define Vv   2000
#define VTt  10000
#define OPTo 16
#define SEQs 10
#define SRCs 40
#define G3   768
#define NB   148

// output layout (flattened tuple, float32)
#define OFF_OPT  164352
#define OFF_TOPO 168448
#define OFF_EX   178688

// ---------------- device scratch ----------------
__device__ float d_gh[Bb*G3];
__device__ float d_gx[Bb*G3];
__device__ float d_ts[Bb*Dd];
__device__ float d_cat[Bb*2*Dd];
__device__ float d_soa[Bb*Dd];
__device__ float d_clog[SEQs*Bb*Vv];
__device__ float d_lse[SEQs*Bb];
__device__ unsigned long long d_amax[Bb];
__device__ unsigned char d_w[SEQs*Bb*Vv];
__device__ int   d_sym[Bb*SEQs];
__device__ __nv_bfloat16 d_Ahi[Bb*SEQs*2*Dd];
__device__ __nv_bfloat16 d_Alo[Bb*SEQs*2*Dd];
__device__ __nv_bfloat16 d_WhiT[(size_t)VTt*2*Dd];
__device__ __nv_bfloat16 d_WloT[(size_t)VTt*2*Dd];

// ---------------- software grid barrier (monotone generation; replay-safe) ----
__device__ unsigned int g_cnt;
__device__ unsigned int g_gen;

__device__ __forceinline__ void gsync() {
    __syncthreads();
    if (threadIdx.x == 0) {
        __threadfence();
        unsigned int gen = *(volatile unsigned int*)&g_gen;
        if (atomicAdd(&g_cnt, 1u) == NB - 1) {
            g_cnt = 0;
            __threadfence();
            atomicAdd(&g_gen, 1u);
        } else {
            while (*(volatile unsigned int*)&g_gen == gen) { __nanosleep(40); }
        }
        __threadfence();
    }
    __syncthreads();
}

__device__ __forceinline__ unsigned f2mono(float f) {
    unsigned u = __float_as_uint(f);
    return (u & 0x80000000u) ? ~u : (u | 0x80000000u);
}

// ---------------- init ----------------
__global__ void k_init(const int* __restrict__ lhs, const float* __restrict__ ts0) {
    int i = blockIdx.x*blockDim.x + threadIdx.x;
    if (i < Bb) d_amax[i] = 0xFFFFFFFFull - (unsigned)lhs[i];   // decode -> lhs
    if (i < Bb*Dd) d_ts[i] = ts0[i];
}

// ---------------- copy small outputs ----------------
__global__ void k_copy(const int* __restrict__ lhs, const int* __restrict__ lmask,
                       const int* __restrict__ gg, float* __restrict__ out) {
    for (int i = blockIdx.x*blockDim.x + threadIdx.x; i < OFF_OPT; i += gridDim.x*blockDim.x) {
        if (i < 256)       out[i] = (float)lhs[i];
        else if (i < 512)  out[i] = (float)lmask[i-256];
        else               out[i] = (float)gg[i-512];
    }
}

// ---------------- generic fp32 SGEMM (only for gh precompute) ----------------
__global__ void sgemm64(const float* __restrict__ A, const float* __restrict__ Bm,
                        const float* __restrict__ bias, float* __restrict__ C,
                        int M, int N, int K) {
    __shared__ float As[64][17];
    __shared__ float Bs[16][65];
    int tid = threadIdx.x;
    int tx = tid & 15, ty = tid >> 4;
    int m0 = blockIdx.y*64, n0 = blockIdx.x*64;
    float acc[4][4];
    #pragma unroll
    for (int i=0;i<4;i++) {
        #pragma unroll
        for (int j=0;j<4;j++) acc[i][j]=0.f;
    }
    for (int k0 = 0; k0 < K; k0 += 16) {
        #pragma unroll
        for (int i = 0; i < 4; i++) {
            int idx = tid + i*256;
            int r = idx >> 4, c = idx & 15;
            As[r][c] = A[(size_t)(m0+r)*K + k0 + c];
        }
        #pragma unroll
        for (int i = 0; i < 4; i++) {
            int idx = tid + i*256;
            int r = idx >> 6, c = idx & 63;
            Bs[r][c] = Bm[(size_t)(k0+r)*N + n0 + c];
        }
        __syncthreads();
        #pragma unroll
        for (int kk = 0; kk < 16; kk++) {
            float a[4], b[4];
            #pragma unroll
            for (int i=0;i<4;i++) a[i] = As[ty*4+i][kk];
            #pragma unroll
            for (int j=0;j<4;j++) b[j] = Bs[kk][tx*4+j];
            #pragma unroll
            for (int i=0;i<4;i++) {
                #pragma unroll
                for (int j=0;j<4;j++) acc[i][j] += a[i]*b[j];
            }
        }
        __syncthreads();
    }
    #pragma unroll
    for (int i=0;i<4;i++) {
        #pragma unroll
        for (int j=0;j<4;j++)
            C[(size_t)(m0+ty*4+i)*N + n0+tx*4+j] = acc[i][j] + bias[n0+tx*4+j];
    }
}

// ---------------- grammar w masks (all steps) ----------------
__global__ void k_w(const int* __restrict__ gg) {
    int tb = blockIdx.x;            // t*B + b
    int t = tb / Bb, b = tb % Bb;
    int tid = threadIdx.x;          // 64 threads
    __shared__ unsigned char ws[Vv];
    __shared__ int f0;
    for (int v = tid; v < Vv; v += 64) ws[v] = 0;
    if (tid == 0) f0 = 0;
    __syncthreads();
    if (tid < OPTo) {
        int base = ((b*OPTo + tid)*4)*SEQs + t;
        int sym = gg[base];
        int m   = gg[base + 3*SEQs];
        if (m) { if (sym > 0) ws[sym] = 1; else f0 = 1; }
    }
    __syncthreads();
    if (tid == 0) ws[0] = (unsigned char)f0;
    __syncthreads();
    unsigned char* outp = d_w + (size_t)tb*Vv;
    for (int v = tid; v < Vv; v += 64) outp[v] = ws[v];
}

// ---------------- prep W: transpose to (VT,512) + hi/lo bf16 ----------------
__global__ void k_prepW(const float* __restrict__ Wtok) {
    __shared__ float tile[32][33];
    int n0 = blockIdx.x*32, k0 = blockIdx.y*32;
    int tx = threadIdx.x, ty = threadIdx.y;   // 32x8
    #pragma unroll
    for (int i=0;i<4;i++) {
        int k = k0 + ty + i*8, n = n0 + tx;
        tile[ty+i*8][tx] = (n < VTt) ? Wtok[(size_t)k*VTt + n] : 0.f;
    }
    __syncthreads();
    #pragma unroll
    for (int i=0;i<4;i++) {
        int n = n0 + ty + i*8, k = k0 + tx;
        if (n < VTt) {
            float v = tile[tx][ty+i*8];
            __nv_bfloat16 h = __float2bfloat16(v);
            d_WhiT[(size_t)n*512 + k] = h;
            d_WloT[(size_t)n*512 + k] = __float2bfloat16(v - __bfloat162float(h));
        }
    }
}

// ============================================================================
// Persistent kernel: entire 10-step loop + lse + opts + prepA. grid=NB=148.
// ============================================================================
__global__ __launch_bounds__(256) void k_persist(
    const float* __restrict__ ts0, const float* __restrict__ emb,
    const float* __restrict__ mem, const float* __restrict__ Wx,
    const float* __restrict__ bx, const float* __restrict__ Wc,
    const float* __restrict__ bc, const float* __restrict__ Wsym,
    const float* __restrict__ bsym, const int* __restrict__ gg,
    float* __restrict__ out)
{
    __shared__ float As[64][17];
    __shared__ float Bs[16][65];
    __shared__ unsigned long long sArg[64*16];
    __shared__ float sGru[Dd + SRCs];
    __shared__ float sVals[OPTo*SEQs];
    __shared__ float sSol[OPTo];
    __shared__ int   sBest;

    const int tid = threadIdx.x;
    const int blk = blockIdx.x;
    const int tx = tid & 15, ty = tid >> 4;
    const int lane = tid & 31, warp = tid >> 5;
    const float LT = logf(1e-13f);

    for (int t = 0; t < SEQs; t++) {
        // ---------- Phase A: gx = emb[argmax_prev] @ Wx + bx  (M=256,N=768,K=256)
        for (int tile = blk; tile < 4*12; tile += NB) {
            int mt = tile / 12, nt = tile % 12;
            int m0 = mt*64, n0 = nt*64;
            float acc[4][4];
            #pragma unroll
            for (int i=0;i<4;i++) {
                #pragma unroll
                for (int j=0;j<4;j++) acc[i][j]=0.f;
            }
            for (int k0 = 0; k0 < Dd; k0 += 16) {
                #pragma unroll
                for (int i = 0; i < 4; i++) {
                    int idx = tid + i*256;
                    int r = idx >> 4, c = idx & 15;
                    unsigned long long p = d_amax[m0 + r];
                    int pr = (int)(0xFFFFFFFFu - (unsigned)(p & 0xFFFFFFFFull));
                    As[r][c] = emb[(size_t)pr*Dd + k0 + c];
                }
                #pragma unroll
                for (int i = 0; i < 4; i++) {
                    int idx = tid + i*256;
                    int r = idx >> 6, c = idx & 63;
                    Bs[r][c] = Wx[(size_t)(k0+r)*G3 + n0 + c];
                }
                __syncthreads();
                #pragma unroll
                for (int kk = 0; kk < 16; kk++) {
                    float a[4], b[4];
                    #pragma unroll
                    for (int i=0;i<4;i++) a[i] = As[ty*4+i][kk];
                    #pragma unroll
                    for (int j=0;j<4;j++) b[j] = Bs[kk][tx*4+j];
                    #pragma unroll
                    for (int i=0;i<4;i++) {
                        #pragma unroll
                        for (int j=0;j<4;j++) acc[i][j] += a[i]*b[j];
                    }
                }
                __syncthreads();
            }
            #pragma unroll
            for (int i=0;i<4;i++) {
                #pragma unroll
                for (int j=0;j<4;j++)
                    d_gx[(size_t)(m0+ty*4+i)*G3 + n0+tx*4+j] = acc[i][j] + bx[n0+tx*4+j];
            }
        }
        gsync();

        // ---------- Phase B: GRU + attention + cat; reset amax
        for (int b = blk; b < Bb; b += NB) {
            int j = tid;
            if (j == 0) d_amax[b] = 0ull;
            float xr = d_gx[b*G3 + j], xz = d_gx[b*G3 + Dd + j], xn = d_gx[b*G3 + 2*Dd + j];
            float hr = d_gh[b*G3 + j], hz = d_gh[b*G3 + Dd + j], hn = d_gh[b*G3 + 2*Dd + j];
            float r = 1.f/(1.f + expf(-(xr+hr)));
            float z = 1.f/(1.f + expf(-(xz+hz)));
            float n = tanhf(xn + r*hn);
            float h = (1.f - z)*n + z*ts0[b*Dd + j];
            sGru[j] = h;
            __syncthreads();
            float* att = sGru + Dd;
            for (int s = warp; s < SRCs; s += 8) {
                const float* mrow = mem + ((size_t)b*SRCs + s)*Dd;
                float sum = 0.f;
                for (int k = lane; k < Dd; k += 32) sum += sGru[k]*mrow[k];
                #pragma unroll
                for (int o=16;o;o>>=1) sum += __shfl_down_sync(0xffffffffu, sum, o);
                if (lane == 0) att[s] = sum;
            }
            __syncthreads();
            if (tid == 0) {
                float m = att[0];
                for (int s=1;s<SRCs;s++) m = fmaxf(m, att[s]);
                float ss = 0.f;
                for (int s=0;s<SRCs;s++){ att[s] = expf(att[s]-m); ss += att[s]; }
                float inv = 1.f/ss;
                for (int s=0;s<SRCs;s++) att[s] *= inv;
            }
            __syncthreads();
            float ctx = 0.f;
            for (int s=0;s<SRCs;s++) ctx += att[s]*mem[((size_t)b*SRCs+s)*Dd + j];
            d_cat[b*2*Dd + j]      = ctx;
            d_cat[b*2*Dd + Dd + j] = h;
            __syncthreads();
        }
        gsync();

        // ---------- Phase C: soa = tanh(cat @ Wc + bc); ts = tanh(ts + soa)
        for (int tile = blk; tile < 4*4; tile += NB) {
            int mt = tile / 4, nt = tile % 4;
            int m0 = mt*64, n0 = nt*64;
            float acc[4][4];
            #pragma unroll
            for (int i=0;i<4;i++) {
                #pragma unroll
                for (int j=0;j<4;j++) acc[i][j]=0.f;
            }
            for (int k0 = 0; k0 < 2*Dd; k0 += 16) {
                #pragma unroll
                for (int i = 0; i < 4; i++) {
                    int idx = tid + i*256;
                    int r = idx >> 4, c = idx & 15;
                    As[r][c] = d_cat[(size_t)(m0+r)*2*Dd + k0 + c];
                }
                #pragma unroll
                for (int i = 0; i < 4; i++) {
                    int idx = tid + i*256;
                    int r = idx >> 6, c = idx & 63;
                    Bs[r][c] = Wc[(size_t)(k0+r)*Dd + n0 + c];
                }
                __syncthreads();
                #pragma unroll
                for (int kk = 0; kk < 16; kk++) {
                    float a[4], b[4];
                    #pragma unroll
                    for (int i=0;i<4;i++) a[i] = As[ty*4+i][kk];
                    #pragma unroll
                    for (int j=0;j<4;j++) b[j] = Bs[kk][tx*4+j];
                    #pragma unroll
                    for (int i=0;i<4;i++) {
                        #pragma unroll
                        for (int j=0;j<4;j++) acc[i][j] += a[i]*b[j];
                    }
                }
                __syncthreads();
            }
            #pragma unroll
            for (int i=0;i<4;i++) {
                #pragma unroll
                for (int j=0;j<4;j++) {
                    int r = m0+ty*4+i, c = n0+tx*4+j;
                    float s = tanhf(acc[i][j] + bc[c]);
                    d_soa[(size_t)r*Dd + c] = s;
                    d_ts[(size_t)r*Dd + c] = tanhf(d_ts[(size_t)r*Dd + c] + s);
                }
            }
        }
        gsync();

        // ---------- Phase D: clog = soa @ Wsym + bsym + mask; argmax via atomicMax
        for (int tile = blk; tile < 4*32; tile += NB) {
            int mt = tile / 32, nt = tile % 32;
            int m0 = mt*64, n0 = nt*64;
            float acc[4][4];
            #pragma unroll
            for (int i=0;i<4;i++) {
                #pragma unroll
                for (int j=0;j<4;j++) acc[i][j]=0.f;
            }
            for (int k0 = 0; k0 < Dd; k0 += 16) {
                #pragma unroll
                for (int i = 0; i < 4; i++) {
                    int idx = tid + i*256;
                    int r = idx >> 4, c = idx & 15;
                    As[r][c] = d_soa[(size_t)(m0+r)*Dd + k0 + c];
                }
                #pragma unroll
                for (int i = 0; i < 4; i++) {
                    int idx = tid + i*256;
                    int r = idx >> 6, c = idx & 63;
                    int gc = n0 + c;
                    Bs[r][c] = (gc < Vv) ? Wsym[(size_t)(k0+r)*Vv + gc] : 0.f;
                }
                __syncthreads();
                #pragma unroll
                for (int kk = 0; kk < 16; kk++) {
                    float a[4], b[4];
                    #pragma unroll
                    for (int i=0;i<4;i++) a[i] = As[ty*4+i][kk];
                    #pragma unroll
                    for (int j=0;j<4;j++) b[j] = Bs[kk][tx*4+j];
                    #pragma unroll
                    for (int i=0;i<4;i++) {
                        #pragma unroll
                        for (int j=0;j<4;j++) acc[i][j] += a[i]*b[j];
                    }
                }
                __syncthreads();
            }
            #pragma unroll
            for (int i=0;i<4;i++) {
                int r = m0+ty*4+i;
                unsigned long long best = 0ull;
                const unsigned char* wr = d_w + ((size_t)t*Bb + r)*Vv;
                float* crow = d_clog + ((size_t)t*Bb + r)*Vv;
                #pragma unroll
                for (int j=0;j<4;j++) {
                    int c = n0+tx*4+j;
                    if (c < Vv) {
                        float v = acc[i][j] + bsym[c];
                        if (!wr[c]) v += LT;
                        crow[c] = v;
                        unsigned long long pk = ((unsigned long long)f2mono(v) << 32)
                                              | (0xFFFFFFFFu - (unsigned)c);
                        if (pk > best) best = pk;
                    }
                }
                sArg[(ty*4+i)*16 + tx] = best;
            }
            __syncthreads();
            if (tid < 64) {
                unsigned long long best = 0ull;
                #pragma unroll
                for (int q=0;q<16;q++) {
                    unsigned long long v = sArg[tid*16 + q];
                    if (v > best) best = v;
                }
                if (best) atomicMax(&d_amax[m0 + tid], best);
            }
            __syncthreads();
        }
        gsync();
    }

    // ---------- Phase L: logsumexp per (t,b), warp per row
    for (int tb = blk*8 + warp; tb < SEQs*Bb; tb += NB*8) {
        const float* row = d_clog + (size_t)tb*Vv;
        float m = -1e30f;
        for (int v = lane; v < Vv; v += 32) m = fmaxf(m, row[v]);
        #pragma unroll
        for (int o=16;o;o>>=1) m = fmaxf(m, __shfl_xor_sync(0xffffffffu, m, o));
        float s = 0.f;
        for (int v = lane; v < Vv; v += 32) s += expf(row[v]-m);
        #pragma unroll
        for (int o=16;o;o>>=1) s += __shfl_xor_sync(0xffffffffu, s, o);
        if (lane == 0) d_lse[tb] = m + logf(s);
    }
    gsync();

    // ---------- Phase O: opts_logp, best, topo
    for (int b = blk; b < Bb; b += NB) {
        if (tid < OPTo*SEQs) {
            int o = tid / SEQs, t = tid % SEQs;
            int base = ((b*OPTo + o)*4)*SEQs + t;
            int m = gg[base + 3*SEQs];
            float v = 0.f;
            if (m) {
                int sym = gg[base];
                v = logf(expf(d_clog[((size_t)t*Bb + b)*Vv + sym] - d_lse[t*Bb + b]) + 1e-13f);
            }
            sVals[tid] = v;
        }
        __syncthreads();
        if (tid < OPTo) {
            float s = 0.f;
            #pragma unroll
            for (int t=0;t<SEQs;t++) s += sVals[tid*SEQs + t];
            sSol[tid] = s;
            out[OFF_OPT + b*OPTo + tid] = s;
        }
        __syncthreads();
        if (tid == 0) {
            int bi = 0; float bv = sSol[0];
            for (int o=1;o<OPTo;o++) if (sSol[o] > bv) { bv = sSol[o]; bi = o; }
            sBest = bi;
        }
        __syncthreads();
        if (tid < 4*SEQs) {
            int c = tid / SEQs, s = tid % SEQs;
            int val = gg[((b*OPTo + sBest)*4 + c)*SEQs + s];
            out[OFF_TOPO + c*(Bb*SEQs) + b*SEQs + s] = (float)val;
            if (c == 0) d_sym[b*SEQs + s] = val;
        }
        __syncthreads();
    }
    gsync();

    // ---------- Phase P: prep A rows (hi/lo bf16)
    for (int idx = blk*256 + tid; idx < Bb*SEQs*512; idx += NB*256) {
        int r = idx >> 9, k = idx & 511;
        int b = r / SEQs;
        float v = (k < Dd) ? emb[(size_t)d_sym[r]*Dd + k] : d_ts[b*Dd + (k - Dd)];
        __nv_bfloat16 h = __float2bfloat16(v);
        d_Ahi[idx] = h;
        d_Alo[idx] = __float2bfloat16(v - __bfloat162float(h));
    }
}

// ---------------- exact_logit GEMM: bf16 split mma, 128x128x32 tiles ----------------
#define MMA16816(d, a, b) asm volatile( \
    "mma.sync.aligned.m16n8k16.row.col.f32.bf16.bf16.f32 " \
    "{%0,%1,%2,%3}, {%4,%5,%6,%7}, {%8,%9}, {%0,%1,%2,%3};\n" \
    : "+f"(d[0]), "+f"(d[1]), "+f"(d[2]), "+f"(d[3]) \
    : "r"(a[0]), "r"(a[1]), "r"(a[2]), "r"(a[3]), "r"(b[0]), "r"(b[1]))

#define ASTR 40

__global__ __launch_bounds__(256) void k_exact(const float* __restrict__ btok,
                                               const float* __restrict__ tok,
                                               float* __restrict__ out) {
    __shared__ __nv_bfloat16 sAh[128*ASTR], sAl[128*ASTR], sBh[128*ASTR], sBl[128*ASTR];
    int tid = threadIdx.x;
    int m0 = blockIdx.y*128, n0 = blockIdx.x*128;
    int lane = tid & 31, warp = tid >> 5;
    int wm = warp >> 2, wn = warp & 3;
    int g = lane >> 2, tq = lane & 3;
    float acc[4][4][4];
    #pragma unroll
    for (int i=0;i<4;i++) {
        #pragma unroll
        for (int j=0;j<4;j++) {
            #pragma unroll
            for (int q=0;q<4;q++) acc[i][j][q] = 0.f;
        }
    }

    int row = tid >> 1;
    int kh  = (tid & 1) << 4;

    for (int k0 = 0; k0 < 512; k0 += 32) {
        {
            const uint4* p = (const uint4*)(d_Ahi + (size_t)(m0+row)*512 + k0 + kh);
            *(uint4*)&sAh[row*ASTR + kh]     = p[0];
            *(uint4*)&sAh[row*ASTR + kh + 8] = p[1];
            const uint4* q = (const uint4*)(d_Alo + (size_t)(m0+row)*512 + k0 + kh);
            *(uint4*)&sAl[row*ASTR + kh]     = q[0];
            *(uint4*)&sAl[row*ASTR + kh + 8] = q[1];
        }
        {
            int nr = n0 + row;
            uint4 z0 = make_uint4(0,0,0,0);
            uint4 h0 = z0, h1 = z0, l0 = z0, l1 = z0;
            if (nr < VTt) {
                const uint4* p = (const uint4*)(d_WhiT + (size_t)nr*512 + k0 + kh);
                h0 = p[0]; h1 = p[1];
                const uint4* q = (const uint4*)(d_WloT + (size_t)nr*512 + k0 + kh);
                l0 = q[0]; l1 = q[1];
            }
            *(uint4*)&sBh[row*ASTR + kh]     = h0;
            *(uint4*)&sBh[row*ASTR + kh + 8] = h1;
            *(uint4*)&sBl[row*ASTR + kh]     = l0;
            *(uint4*)&sBl[row*ASTR + kh + 8] = l1;
        }
        __syncthreads();
        #pragma unroll
        for (int ks = 0; ks < 2; ks++) {
            int kb = ks*16;
            uint32_t ah[4][4], al[4][4];
            #pragma unroll
            for (int mi=0;mi<4;mi++) {
                int rb = wm*64 + mi*16;
                int c0 = kb + tq*2;
                ah[mi][0] = *(const uint32_t*)&sAh[(rb+g)*ASTR + c0];
                ah[mi][1] = *(const uint32_t*)&sAh[(rb+g+8)*ASTR + c0];
                ah[mi][2] = *(const uint32_t*)&sAh[(rb+g)*ASTR + c0 + 8];
                ah[mi][3] = *(const uint32_t*)&sAh[(rb+g+8)*ASTR + c0 + 8];
                al[mi][0] = *(const uint32_t*)&sAl[(rb+g)*ASTR + c0];
                al[mi][1] = *(const uint32_t*)&sAl[(rb+g+8)*ASTR + c0];
                al[mi][2] = *(const uint32_t*)&sAl[(rb+g)*ASTR + c0 + 8];
                al[mi][3] = *(const uint32_t*)&sAl[(rb+g+8)*ASTR + c0 + 8];
            }
            uint32_t bh[4][2], bl[4][2];
            #pragma unroll
            for (int ni=0;ni<4;ni++) {
                int nb = wn*32 + ni*8 + g;
                bh[ni][0] = *(const uint32_t*)&sBh[nb*ASTR + kb + tq*2];
                bh[ni][1] = *(const uint32_t*)&sBh[nb*ASTR + kb + tq*2 + 8];
                bl[ni][0] = *(const uint32_t*)&sBl[nb*ASTR + kb + tq*2];
                bl[ni][1] = *(const uint32_t*)&sBl[nb*ASTR + kb + tq*2 + 8];
            }
            #pragma unroll
            for (int mi=0;mi<4;mi++) {
                #pragma unroll
                for (int ni=0;ni<4;ni++) {
                    MMA16816(acc[mi][ni], ah[mi], bh[ni]);
                    MMA16816(acc[mi][ni], ah[mi], bl[ni]);
                    MMA16816(acc[mi][ni], al[mi], bh[ni]);
                }
            }
        }
        __syncthreads();
    }
    const float LT = logf(1e-13f);
    #pragma unroll
    for (int mi=0;mi<4;mi++) {
        int r0 = m0 + wm*64 + mi*16 + g;
        int s0 = d_sym[r0];
        int s1 = d_sym[r0 + 8];
        #pragma unroll
        for (int ni=0;ni<4;ni++) {
            int c0 = n0 + wn*32 + ni*8 + tq*2;
            if (c0 < VTt) {
                float b0 = btok[c0];
                out[OFF_EX + (size_t)r0*VTt + c0]     = acc[mi][ni][0] + b0 + (tok[(size_t)s0*VTt + c0] > 0.f ? 0.f : LT);
                out[OFF_EX + (size_t)(r0+8)*VTt + c0] = acc[mi][ni][2] + b0 + (tok[(size_t)s1*VTt + c0] > 0.f ? 0.f : LT);
            }
            if (c0 + 1 < VTt) {
                float b1 = btok[c0+1];
                out[OFF_EX + (size_t)r0*VTt + c0+1]     = acc[mi][ni][1] + b1 + (tok[(size_t)s0*VTt + c0+1] > 0.f ? 0.f : LT);
                out[OFF_EX + (size_t)(r0+8)*VTt + c0+1] = acc[mi][ni][3] + b1 + (tok[(size_t)s1*VTt + c0+1] > 0.f ? 0.f : LT);
            }
        }
    }
}

// ---------------- host launcher ----------------
extern "C" void kernel_launch(void* const* d_in, const int* in_sizes, int n_in,
                              void* d_out, int out_size) {
    const int*   lhs   = (const int*)d_in[0];
    const int*   lmask = (const int*)d_in[1];
    const float* ts0   = (const float*)d_in[2];
    const int*   gg    = (const int*)d_in[3];
    const float* emb   = (const float*)d_in[4];
    const float* mem   = (const float*)d_in[5];
    const float* Wx    = (const float*)d_in[6];
    const float* Wh    = (const float*)d_in[7];
    const float* bx    = (const float*)d_in[8];
    const float* bh    = (const float*)d_in[9];
    const float* Wc    = (const float*)d_in[10];
    const float* bc    = (const float*)d_in[11];
    const float* Wsym  = (const float*)d_in[12];
    const float* bsym  = (const float*)d_in[13];
    const float* Wtok  = (const float*)d_in[14];
    const float* btok  = (const float*)d_in[15];
    const float* tok   = (const float*)d_in[16];
    float* out = (float*)d_out;

    void* pv;
    cudaGetSymbolAddress(&pv, d_gh);   float* p_gh = (float*)pv;

    k_init<<<256, 256>>>(lhs, ts0);
    sgemm64<<<dim3(12,4), 256>>>(ts0, Wh, bh, p_gh, Bb, G3, Dd);   // gh constant
    k_w<<<SEQs*Bb, 64>>>(gg);
    k_copy<<<642, 256>>>(lhs, lmask, gg, out);
    k_prepW<<<dim3((VTt+31)/32, 16), dim3(32,8)>>>(Wtok);

    k_persist<<<NB, 256>>>(ts0, emb, mem, Wx, bx, Wc, bc, Wsym, bsym, gg, out);

    k_exact<<<dim3((VTt+127)/128, (Bb*SEQs)/128), 256>>>(btok, tok, out);
}

// round 4
// speedup vs baseline: 1.3655x; 1.3459x over previous
#include <cuda_runtime.h>
#include <cuda_bf16.h>
#include <cstdint>

#define Bb   256
#define Dd   256
#define Vv   2000
#define VTt  10000
#define OPTo 16
#define SEQs 10
#define SRCs 40
#define G3   768
#define NB   148

// output layout (flattened tuple, float32)
#define OFF_OPT  164352
#define OFF_TOPO 168448
#define OFF_EX   178688

// ---------------- device scratch ----------------
__device__ float d_gh[Bb*G3];
__device__ float d_gx[Bb*G3];
__device__ float d_ts[Bb*Dd];
__device__ float d_cat[Bb*2*Dd];
__device__ float d_soa[Bb*Dd];
__device__ float d_clog[SEQs*Bb*Vv];
__device__ float d_lse[SEQs*Bb];
__device__ unsigned long long d_amax[Bb];
__device__ unsigned char d_w[SEQs*Bb*Vv];
__device__ int   d_sym[Bb*SEQs];
__device__ __nv_bfloat16 d_Ahi[Bb*SEQs*2*Dd];
__device__ __nv_bfloat16 d_WhiT[(size_t)VTt*2*Dd];

// ---------------- software grid barrier (monotone generation; replay-safe) ----
__device__ unsigned int g_cnt;
__device__ unsigned int g_gen;

__device__ __forceinline__ void gsync() {
    __syncthreads();
    if (threadIdx.x == 0) {
        __threadfence();
        unsigned int gen = *(volatile unsigned int*)&g_gen;
        if (atomicAdd(&g_cnt, 1u) == NB - 1) {
            g_cnt = 0;
            __threadfence();
            atomicAdd(&g_gen, 1u);
        } else {
            while (*(volatile unsigned int*)&g_gen == gen) { __nanosleep(40); }
        }
        __threadfence();
    }
    __syncthreads();
}

__device__ __forceinline__ unsigned f2mono(float f) {
    unsigned u = __float_as_uint(f);
    return (u & 0x80000000u) ? ~u : (u | 0x80000000u);
}

// ---------------- init ----------------
__global__ void k_init(const int* __restrict__ lhs, const float* __restrict__ ts0) {
    int i = blockIdx.x*blockDim.x + threadIdx.x;
    if (i < Bb) d_amax[i] = 0xFFFFFFFFull - (unsigned)lhs[i];   // decode -> lhs
    if (i < Bb*Dd) d_ts[i] = ts0[i];
}

// ---------------- copy small outputs ----------------
__global__ void k_copy(const int* __restrict__ lhs, const int* __restrict__ lmask,
                       const int* __restrict__ gg, float* __restrict__ out) {
    for (int i = blockIdx.x*blockDim.x + threadIdx.x; i < OFF_OPT; i += gridDim.x*blockDim.x) {
        if (i < 256)       out[i] = (float)lhs[i];
        else if (i < 512)  out[i] = (float)lmask[i-256];
        else               out[i] = (float)gg[i-512];
    }
}

// ---------------- generic fp32 SGEMM (only for gh precompute) ----------------
__global__ void sgemm64(const float* __restrict__ A, const float* __restrict__ Bm,
                        const float* __restrict__ bias, float* __restrict__ C,
                        int M, int N, int K) {
    __shared__ float As[64][17];
    __shared__ float Bs[16][65];
    int tid = threadIdx.x;
    int tx = tid & 15, ty = tid >> 4;
    int m0 = blockIdx.y*64, n0 = blockIdx.x*64;
    float acc[4][4];
    #pragma unroll
    for (int i=0;i<4;i++) {
        #pragma unroll
        for (int j=0;j<4;j++) acc[i][j]=0.f;
    }
    for (int k0 = 0; k0 < K; k0 += 16) {
        #pragma unroll
        for (int i = 0; i < 4; i++) {
            int idx = tid + i*256;
            int r = idx >> 4, c = idx & 15;
            As[r][c] = A[(size_t)(m0+r)*K + k0 + c];
        }
        #pragma unroll
        for (int i = 0; i < 4; i++) {
            int idx = tid + i*256;
            int r = idx >> 6, c = idx & 63;
            Bs[r][c] = Bm[(size_t)(k0+r)*N + n0 + c];
        }
        __syncthreads();
        #pragma unroll
        for (int kk = 0; kk < 16; kk++) {
            float a[4], b[4];
            #pragma unroll
            for (int i=0;i<4;i++) a[i] = As[ty*4+i][kk];
            #pragma unroll
            for (int j=0;j<4;j++) b[j] = Bs[kk][tx*4+j];
            #pragma unroll
            for (int i=0;i<4;i++) {
                #pragma unroll
                for (int j=0;j<4;j++) acc[i][j] += a[i]*b[j];
            }
        }
        __syncthreads();
    }
    #pragma unroll
    for (int i=0;i<4;i++) {
        #pragma unroll
        for (int j=0;j<4;j++)
            C[(size_t)(m0+ty*4+i)*N + n0+tx*4+j] = acc[i][j] + bias[n0+tx*4+j];
    }
}

// ---------------- grammar w masks (all steps) ----------------
__global__ void k_w(const int* __restrict__ gg) {
    int tb = blockIdx.x;            // t*B + b
    int t = tb / Bb, b = tb % Bb;
    int tid = threadIdx.x;          // 64 threads
    __shared__ unsigned char ws[Vv];
    __shared__ int f0;
    for (int v = tid; v < Vv; v += 64) ws[v] = 0;
    if (tid == 0) f0 = 0;
    __syncthreads();
    if (tid < OPTo) {
        int base = ((b*OPTo + tid)*4)*SEQs + t;
        int sym = gg[base];
        int m   = gg[base + 3*SEQs];
        if (m) { if (sym > 0) ws[sym] = 1; else f0 = 1; }
    }
    __syncthreads();
    if (tid == 0) ws[0] = (unsigned char)f0;
    __syncthreads();
    unsigned char* outp = d_w + (size_t)tb*Vv;
    for (int v = tid; v < Vv; v += 64) outp[v] = ws[v];
}

// ---------------- prep W: transpose to (VT,512) bf16 ----------------
__global__ void k_prepW(const float* __restrict__ Wtok) {
    __shared__ float tile[32][33];
    int n0 = blockIdx.x*32, k0 = blockIdx.y*32;
    int tx = threadIdx.x, ty = threadIdx.y;   // 32x8
    #pragma unroll
    for (int i=0;i<4;i++) {
        int k = k0 + ty + i*8, n = n0 + tx;
        tile[ty+i*8][tx] = (n < VTt) ? Wtok[(size_t)k*VTt + n] : 0.f;
    }
    __syncthreads();
    #pragma unroll
    for (int i=0;i<4;i++) {
        int n = n0 + ty + i*8, k = k0 + tx;
        if (n < VTt)
            d_WhiT[(size_t)n*512 + k] = __float2bfloat16(tile[tx][ty+i*8]);
    }
}

// ============================================================================
// Persistent kernel: entire 10-step loop + lse + opts + prepA. grid=NB=148.
// ============================================================================
__global__ __launch_bounds__(256) void k_persist(
    const float* __restrict__ ts0, const float* __restrict__ emb,
    const float* __restrict__ mem, const float* __restrict__ Wx,
    const float* __restrict__ bx, const float* __restrict__ Wc,
    const float* __restrict__ bc, const float* __restrict__ Wsym,
    const float* __restrict__ bsym, const int* __restrict__ gg,
    float* __restrict__ out)
{
    __shared__ float As[64][17];
    __shared__ float Bs[16][65];
    __shared__ unsigned long long sArg[64*16];
    __shared__ float sGru[Dd + SRCs];
    __shared__ float sVals[OPTo*SEQs];
    __shared__ float sSol[OPTo];
    __shared__ int   sBest;

    const int tid = threadIdx.x;
    const int blk = blockIdx.x;
    const int tx = tid & 15, ty = tid >> 4;
    const int lane = tid & 31, warp = tid >> 5;
    const float LT = logf(1e-13f);

    for (int t = 0; t < SEQs; t++) {
        // ---------- Phase A: gx = emb[argmax_prev] @ Wx + bx  (32x64 tiles, 96)
        for (int tile = blk; tile < 96; tile += NB) {
            int mt = tile / 12, nt = tile % 12;
            int m0 = mt*32, n0 = nt*64;
            float acc[2][4];
            #pragma unroll
            for (int i=0;i<2;i++) {
                #pragma unroll
                for (int j=0;j<4;j++) acc[i][j]=0.f;
            }
            for (int k0 = 0; k0 < Dd; k0 += 16) {
                {
                    int idx = tid*2;
                    int r = idx >> 4, c = idx & 15;
                    unsigned long long p = d_amax[m0 + r];
                    int pr = (int)(0xFFFFFFFFu - (unsigned)(p & 0xFFFFFFFFull));
                    const float* er = emb + (size_t)pr*Dd + k0;
                    As[r][c]   = er[c];
                    As[r][c+1] = er[c+1];
                }
                {
                    int idx = tid*4;
                    int r = idx >> 6, c = idx & 63;
                    const float* wr_ = Wx + (size_t)(k0+r)*G3 + n0 + c;
                    Bs[r][c] = wr_[0]; Bs[r][c+1] = wr_[1];
                    Bs[r][c+2] = wr_[2]; Bs[r][c+3] = wr_[3];
                }
                __syncthreads();
                #pragma unroll
                for (int kk = 0; kk < 16; kk++) {
                    float a[2], b[4];
                    #pragma unroll
                    for (int i=0;i<2;i++) a[i] = As[ty*2+i][kk];
                    #pragma unroll
                    for (int j=0;j<4;j++) b[j] = Bs[kk][tx*4+j];
                    #pragma unroll
                    for (int i=0;i<2;i++) {
                        #pragma unroll
                        for (int j=0;j<4;j++) acc[i][j] += a[i]*b[j];
                    }
                }
                __syncthreads();
            }
            #pragma unroll
            for (int i=0;i<2;i++) {
                #pragma unroll
                for (int j=0;j<4;j++)
                    d_gx[(size_t)(m0+ty*2+i)*G3 + n0+tx*4+j] = acc[i][j] + bx[n0+tx*4+j];
            }
        }
        gsync();

        // ---------- Phase B: GRU + attention + cat; reset amax
        for (int b = blk; b < Bb; b += NB) {
            int j = tid;
            if (j == 0) d_amax[b] = 0ull;
            float xr = d_gx[b*G3 + j], xz = d_gx[b*G3 + Dd + j], xn = d_gx[b*G3 + 2*Dd + j];
            float hr = d_gh[b*G3 + j], hz = d_gh[b*G3 + Dd + j], hn = d_gh[b*G3 + 2*Dd + j];
            float r = 1.f/(1.f + expf(-(xr+hr)));
            float z = 1.f/(1.f + expf(-(xz+hz)));
            float n = tanhf(xn + r*hn);
            float h = (1.f - z)*n + z*ts0[b*Dd + j];
            sGru[j] = h;
            __syncthreads();
            float* att = sGru + Dd;
            for (int s = warp; s < SRCs; s += 8) {
                const float* mrow = mem + ((size_t)b*SRCs + s)*Dd;
                float sum = 0.f;
                for (int k = lane; k < Dd; k += 32) sum += sGru[k]*mrow[k];
                #pragma unroll
                for (int o=16;o;o>>=1) sum += __shfl_down_sync(0xffffffffu, sum, o);
                if (lane == 0) att[s] = sum;
            }
            __syncthreads();
            if (tid == 0) {
                float m = att[0];
                for (int s=1;s<SRCs;s++) m = fmaxf(m, att[s]);
                float ss = 0.f;
                for (int s=0;s<SRCs;s++){ att[s] = expf(att[s]-m); ss += att[s]; }
                float inv = 1.f/ss;
                for (int s=0;s<SRCs;s++) att[s] *= inv;
            }
            __syncthreads();
            float ctx = 0.f;
            for (int s=0;s<SRCs;s++) ctx += att[s]*mem[((size_t)b*SRCs+s)*Dd + j];
            d_cat[b*2*Dd + j]      = ctx;
            d_cat[b*2*Dd + Dd + j] = h;
            __syncthreads();
        }
        gsync();

        // ---------- Phase C: soa = tanh(cat @ Wc + bc); ts = tanh(ts + soa)  (32x32, 64)
        for (int tile = blk; tile < 64; tile += NB) {
            int mt = tile >> 3, nt = tile & 7;
            int m0 = mt*32, n0 = nt*32;
            float acc[2][2];
            acc[0][0]=acc[0][1]=acc[1][0]=acc[1][1]=0.f;
            for (int k0 = 0; k0 < 2*Dd; k0 += 16) {
                {
                    int idx = tid*2;
                    int r = idx >> 4, c = idx & 15;
                    const float* cr = d_cat + (size_t)(m0+r)*2*Dd + k0 + c;
                    As[r][c] = cr[0]; As[r][c+1] = cr[1];
                }
                {
                    int idx = tid*2;
                    int r = idx >> 5, c = idx & 31;
                    const float* wr_ = Wc + (size_t)(k0+r)*Dd + n0 + c;
                    Bs[r][c] = wr_[0]; Bs[r][c+1] = wr_[1];
                }
                __syncthreads();
                #pragma unroll
                for (int kk = 0; kk < 16; kk++) {
                    float a[2], b[2];
                    a[0] = As[ty*2][kk]; a[1] = As[ty*2+1][kk];
                    b[0] = Bs[kk][tx*2]; b[1] = Bs[kk][tx*2+1];
                    acc[0][0] += a[0]*b[0]; acc[0][1] += a[0]*b[1];
                    acc[1][0] += a[1]*b[0]; acc[1][1] += a[1]*b[1];
                }
                __syncthreads();
            }
            #pragma unroll
            for (int i=0;i<2;i++) {
                #pragma unroll
                for (int j=0;j<2;j++) {
                    int r = m0+ty*2+i, c = n0+tx*2+j;
                    float s = tanhf(acc[i][j] + bc[c]);
                    d_soa[(size_t)r*Dd + c] = s;
                    d_ts[(size_t)r*Dd + c] = tanhf(d_ts[(size_t)r*Dd + c] + s);
                }
            }
        }
        gsync();

        // ---------- Phase D: clog = soa @ Wsym + bsym + mask; argmax via atomicMax
        for (int tile = blk; tile < 4*32; tile += NB) {
            int mt = tile / 32, nt = tile % 32;
            int m0 = mt*64, n0 = nt*64;
            float acc[4][4];
            #pragma unroll
            for (int i=0;i<4;i++) {
                #pragma unroll
                for (int j=0;j<4;j++) acc[i][j]=0.f;
            }
            for (int k0 = 0; k0 < Dd; k0 += 16) {
                #pragma unroll
                for (int i = 0; i < 4; i++) {
                    int idx = tid + i*256;
                    int r = idx >> 4, c = idx & 15;
                    As[r][c] = d_soa[(size_t)(m0+r)*Dd + k0 + c];
                }
                #pragma unroll
                for (int i = 0; i < 4; i++) {
                    int idx = tid + i*256;
                    int r = idx >> 6, c = idx & 63;
                    int gc = n0 + c;
                    Bs[r][c] = (gc < Vv) ? Wsym[(size_t)(k0+r)*Vv + gc] : 0.f;
                }
                __syncthreads();
                #pragma unroll
                for (int kk = 0; kk < 16; kk++) {
                    float a[4], b[4];
                    #pragma unroll
                    for (int i=0;i<4;i++) a[i] = As[ty*4+i][kk];
                    #pragma unroll
                    for (int j=0;j<4;j++) b[j] = Bs[kk][tx*4+j];
                    #pragma unroll
                    for (int i=0;i<4;i++) {
                        #pragma unroll
                        for (int j=0;j<4;j++) acc[i][j] += a[i]*b[j];
                    }
                }
                __syncthreads();
            }
            #pragma unroll
            for (int i=0;i<4;i++) {
                int r = m0+ty*4+i;
                unsigned long long best = 0ull;
                const unsigned char* wr = d_w + ((size_t)t*Bb + r)*Vv;
                float* crow = d_clog + ((size_t)t*Bb + r)*Vv;
                #pragma unroll
                for (int j=0;j<4;j++) {
                    int c = n0+tx*4+j;
                    if (c < Vv) {
                        float v = acc[i][j] + bsym[c];
                        if (!wr[c]) v += LT;
                        crow[c] = v;
                        unsigned long long pk = ((unsigned long long)f2mono(v) << 32)
                                              | (0xFFFFFFFFu - (unsigned)c);
                        if (pk > best) best = pk;
                    }
                }
                sArg[(ty*4+i)*16 + tx] = best;
            }
            __syncthreads();
            if (tid < 64) {
                unsigned long long best = 0ull;
                #pragma unroll
                for (int q=0;q<16;q++) {
                    unsigned long long v = sArg[tid*16 + q];
                    if (v > best) best = v;
                }
                if (best) atomicMax(&d_amax[m0 + tid], best);
            }
            __syncthreads();
        }
        gsync();
    }

    // ---------- Phase L: logsumexp per (t,b), warp per row
    for (int tb = blk*8 + warp; tb < SEQs*Bb; tb += NB*8) {
        const float* row = d_clog + (size_t)tb*Vv;
        float m = -1e30f;
        for (int v = lane; v < Vv; v += 32) m = fmaxf(m, row[v]);
        #pragma unroll
        for (int o=16;o;o>>=1) m = fmaxf(m, __shfl_xor_sync(0xffffffffu, m, o));
        float s = 0.f;
        for (int v = lane; v < Vv; v += 32) s += expf(row[v]-m);
        #pragma unroll
        for (int o=16;o;o>>=1) s += __shfl_xor_sync(0xffffffffu, s, o);
        if (lane == 0) d_lse[tb] = m + logf(s);
    }
    gsync();

    // ---------- Phase O: opts_logp, best, topo
    for (int b = blk; b < Bb; b += NB) {
        if (tid < OPTo*SEQs) {
            int o = tid / SEQs, t = tid % SEQs;
            int base = ((b*OPTo + o)*4)*SEQs + t;
            int m = gg[base + 3*SEQs];
            float v = 0.f;
            if (m) {
                int sym = gg[base];
                v = logf(expf(d_clog[((size_t)t*Bb + b)*Vv + sym] - d_lse[t*Bb + b]) + 1e-13f);
            }
            sVals[tid] = v;
        }
        __syncthreads();
        if (tid < OPTo) {
            float s = 0.f;
            #pragma unroll
            for (int t=0;t<SEQs;t++) s += sVals[tid*SEQs + t];
            sSol[tid] = s;
            out[OFF_OPT + b*OPTo + tid] = s;
        }
        __syncthreads();
        if (tid == 0) {
            int bi = 0; float bv = sSol[0];
            for (int o=1;o<OPTo;o++) if (sSol[o] > bv) { bv = sSol[o]; bi = o; }
            sBest = bi;
        }
        __syncthreads();
        if (tid < 4*SEQs) {
            int c = tid / SEQs, s = tid % SEQs;
            int val = gg[((b*OPTo + sBest)*4 + c)*SEQs + s];
            out[OFF_TOPO + c*(Bb*SEQs) + b*SEQs + s] = (float)val;
            if (c == 0) d_sym[b*SEQs + s] = val;
        }
        __syncthreads();
    }
    gsync();

    // ---------- Phase P: prep A rows (bf16)
    for (int idx = blk*256 + tid; idx < Bb*SEQs*512; idx += NB*256) {
        int r = idx >> 9, k = idx & 511;
        int b = r / SEQs;
        float v = (k < Dd) ? emb[(size_t)d_sym[r]*Dd + k] : d_ts[b*Dd + (k - Dd)];
        d_Ahi[idx] = __float2bfloat16(v);
    }
}

// ---------------- exact_logit GEMM: single bf16 mma, 128x128x32, double-buffered --
#define MMA16816(d, a, b) asm volatile( \
    "mma.sync.aligned.m16n8k16.row.col.f32.bf16.bf16.f32 " \
    "{%0,%1,%2,%3}, {%4,%5,%6,%7}, {%8,%9}, {%0,%1,%2,%3};\n" \
    : "+f"(d[0]), "+f"(d[1]), "+f"(d[2]), "+f"(d[3]) \
    : "r"(a[0]), "r"(a[1]), "r"(a[2]), "r"(a[3]), "r"(b[0]), "r"(b[1]))

#define ASTR 40

__global__ __launch_bounds__(256) void k_exact(const float* __restrict__ btok,
                                               const float* __restrict__ tok,
                                               float* __restrict__ out) {
    __shared__ __nv_bfloat16 sA[2][128*ASTR], sB[2][128*ASTR];
    int tid = threadIdx.x;
    int m0 = blockIdx.y*128, n0 = blockIdx.x*128;
    int lane = tid & 31, warp = tid >> 5;
    int wm = warp >> 2, wn = warp & 3;
    int g = lane >> 2, tq = lane & 3;
    float acc[4][4][4];
    #pragma unroll
    for (int i=0;i<4;i++) {
        #pragma unroll
        for (int j=0;j<4;j++) {
            #pragma unroll
            for (int q=0;q<4;q++) acc[i][j][q] = 0.f;
        }
    }

    int row = tid >> 1;
    int kh  = (tid & 1) << 4;
    int nr  = n0 + row;
    const bool nok = (nr < VTt);

    uint4 ra0, ra1, rb0, rb1;
    const uint4 z0 = make_uint4(0,0,0,0);

    // prefetch k0 = 0
    {
        const uint4* p = (const uint4*)(d_Ahi + (size_t)(m0+row)*512 + kh);
        ra0 = p[0]; ra1 = p[1];
        rb0 = z0; rb1 = z0;
        if (nok) {
            const uint4* q = (const uint4*)(d_WhiT + (size_t)nr*512 + kh);
            rb0 = q[0]; rb1 = q[1];
        }
    }
    *(uint4*)&sA[0][row*ASTR + kh]     = ra0;
    *(uint4*)&sA[0][row*ASTR + kh + 8] = ra1;
    *(uint4*)&sB[0][row*ASTR + kh]     = rb0;
    *(uint4*)&sB[0][row*ASTR + kh + 8] = rb1;
    __syncthreads();

    int buf = 0;
    for (int k0 = 0; k0 < 512; k0 += 32) {
        int nxt = k0 + 32;
        if (nxt < 512) {
            const uint4* p = (const uint4*)(d_Ahi + (size_t)(m0+row)*512 + nxt + kh);
            ra0 = p[0]; ra1 = p[1];
            rb0 = z0; rb1 = z0;
            if (nok) {
                const uint4* q = (const uint4*)(d_WhiT + (size_t)nr*512 + nxt + kh);
                rb0 = q[0]; rb1 = q[1];
            }
        }
        const __nv_bfloat16* cA = sA[buf];
        const __nv_bfloat16* cB = sB[buf];
        #pragma unroll
        for (int ks = 0; ks < 2; ks++) {
            int kb = ks*16;
            uint32_t ah[4][4];
            #pragma unroll
            for (int mi=0;mi<4;mi++) {
                int rb = wm*64 + mi*16;
                int c0 = kb + tq*2;
                ah[mi][0] = *(const uint32_t*)&cA[(rb+g)*ASTR + c0];
                ah[mi][1] = *(const uint32_t*)&cA[(rb+g+8)*ASTR + c0];
                ah[mi][2] = *(const uint32_t*)&cA[(rb+g)*ASTR + c0 + 8];
                ah[mi][3] = *(const uint32_t*)&cA[(rb+g+8)*ASTR + c0 + 8];
            }
            uint32_t bh[4][2];
            #pragma unroll
            for (int ni=0;ni<4;ni++) {
                int nb = wn*32 + ni*8 + g;
                bh[ni][0] = *(const uint32_t*)&cB[nb*ASTR + kb + tq*2];
                bh[ni][1] = *(const uint32_t*)&cB[nb*ASTR + kb + tq*2 + 8];
            }
            #pragma unroll
            for (int mi=0;mi<4;mi++) {
                #pragma unroll
                for (int ni=0;ni<4;ni++) {
                    MMA16816(acc[mi][ni], ah[mi], bh[ni]);
                }
            }
        }
        if (nxt < 512) {
            *(uint4*)&sA[buf^1][row*ASTR + kh]     = ra0;
            *(uint4*)&sA[buf^1][row*ASTR + kh + 8] = ra1;
            *(uint4*)&sB[buf^1][row*ASTR + kh]     = rb0;
            *(uint4*)&sB[buf^1][row*ASTR + kh + 8] = rb1;
            __syncthreads();
            buf ^= 1;
        }
    }

    const float LT = logf(1e-13f);
    #pragma unroll
    for (int mi=0;mi<4;mi++) {
        int r0 = m0 + wm*64 + mi*16 + g;
        int s0 = d_sym[r0];
        int s1 = d_sym[r0 + 8];
        #pragma unroll
        for (int ni=0;ni<4;ni++) {
            int c0 = n0 + wn*32 + ni*8 + tq*2;
            if (c0 < VTt) {
                float b0 = btok[c0];
                out[OFF_EX + (size_t)r0*VTt + c0]     = acc[mi][ni][0] + b0 + (tok[(size_t)s0*VTt + c0] > 0.f ? 0.f : LT);
                out[OFF_EX + (size_t)(r0+8)*VTt + c0] = acc[mi][ni][2] + b0 + (tok[(size_t)s1*VTt + c0] > 0.f ? 0.f : LT);
            }
            if (c0 + 1 < VTt) {
                float b1 = btok[c0+1];
                out[OFF_EX + (size_t)r0*VTt + c0+1]     = acc[mi][ni][1] + b1 + (tok[(size_t)s0*VTt + c0+1] > 0.f ? 0.f : LT);
                out[OFF_EX + (size_t)(r0+8)*VTt + c0+1] = acc[mi][ni][3] + b1 + (tok[(size_t)s1*VTt + c0+1] > 0.f ? 0.f : LT);
            }
        }
    }
}

// ---------------- host launcher ----------------
extern "C" void kernel_launch(void* const* d_in, const int* in_sizes, int n_in,
                              void* d_out, int out_size) {
    const int*   lhs   = (const int*)d_in[0];
    const int*   lmask = (const int*)d_in[1];
    const float* ts0   = (const float*)d_in[2];
    const int*   gg    = (const int*)d_in[3];
    const float* emb   = (const float*)d_in[4];
    const float* mem   = (const float*)d_in[5];
    const float* Wx    = (const float*)d_in[6];
    const float* Wh    = (const float*)d_in[7];
    const float* bx    = (const float*)d_in[8];
    const float* bh    = (const float*)d_in[9];
    const float* Wc    = (const float*)d_in[10];
    const float* bc    = (const float*)d_in[11];
    const float* Wsym  = (const float*)d_in[12];
    const float* bsym  = (const float*)d_in[13];
    const float* Wtok  = (const float*)d_in[14];
    const float* btok  = (const float*)d_in[15];
    const float* tok   = (const float*)d_in[16];
    float* out = (float*)d_out;

    void* pv;
    cudaGetSymbolAddress(&pv, d_gh);   float* p_gh = (float*)pv;

    k_init<<<256, 256>>>(lhs, ts0);
    sgemm64<<<dim3(12,4), 256>>>(ts0, Wh, bh, p_gh, Bb, G3, Dd);   // gh constant
    k_w<<<SEQs*Bb, 64>>>(gg);
    k_copy<<<642, 256>>>(lhs, lmask, gg, out);
    k_prepW<<<dim3((VTt+31)/32, 16), dim3(32,8)>>>(Wtok);

    k_persist<<<NB, 256>>>(ts0, emb, mem, Wx, bx, Wc, bc, Wsym, bsym, gg, out);

    k_exact<<<dim3((VTt+127)/128, (Bb*SEQs)/128), 256>>>(btok, tok, out);
}

// round 5
// speedup vs baseline: 1.7259x; 1.2639x over previous
#include <cuda_runtime.h>
#include <cuda_bf16.h>
#include <cstdint>

#define Bb   256
#define Dd   256
#define Vv   2000
#define VTt  10000
#define OPTo 16
#define SEQs 10
#define SRCs 40
#define G3   768
#define NB   148

// output layout (flattened tuple, float32)
#define OFF_OPT  164352
#define OFF_TOPO 168448
#define OFF_EX   178688

// ---------------- device scratch ----------------
__device__ float d_gh[Bb*G3];
__device__ float d_gx[Bb*G3];
__device__ float d_ts[Bb*Dd];
__device__ float d_cat[Bb*2*Dd];
__device__ float d_clog[SEQs*Bb*Vv];
__device__ float d_lse[SEQs*Bb];
__device__ unsigned long long d_amax[Bb];
__device__ unsigned char d_w[SEQs*Bb*Vv];
__device__ int   d_sym[Bb*SEQs];
__device__ __nv_bfloat16 d_soaHi[Bb*Dd];
__device__ __nv_bfloat16 d_soaLo[Bb*Dd];
__device__ __nv_bfloat16 d_embHi[Vv*Dd];
__device__ __nv_bfloat16 d_embLo[Vv*Dd];
__device__ __nv_bfloat16 d_WxHiT[G3*Dd];
__device__ __nv_bfloat16 d_WxLoT[G3*Dd];
__device__ __nv_bfloat16 d_WsymHiT[2048*Dd];
__device__ __nv_bfloat16 d_WsymLoT[2048*Dd];
__device__ __nv_bfloat16 d_Ahi[Bb*SEQs*2*Dd];
__device__ __nv_bfloat16 d_WhiT[(size_t)VTt*2*Dd];

// ---------------- software grid barrier ----------------
__device__ unsigned int g_cnt;
__device__ unsigned int g_gen;

__device__ __forceinline__ void gsync() {
    __syncthreads();
    if (threadIdx.x == 0) {
        __threadfence();
        unsigned int gen = *(volatile unsigned int*)&g_gen;
        if (atomicAdd(&g_cnt, 1u) == NB - 1) {
            g_cnt = 0;
            __threadfence();
            atomicAdd(&g_gen, 1u);
        } else {
            while (*(volatile unsigned int*)&g_gen == gen) { __nanosleep(40); }
        }
        __threadfence();
    }
    __syncthreads();
}

__device__ __forceinline__ unsigned f2mono(float f) {
    unsigned u = __float_as_uint(f);
    return (u & 0x80000000u) ? ~u : (u | 0x80000000u);
}

#define MMA16816(d, a, b) asm volatile( \
    "mma.sync.aligned.m16n8k16.row.col.f32.bf16.bf16.f32 " \
    "{%0,%1,%2,%3}, {%4,%5,%6,%7}, {%8,%9}, {%0,%1,%2,%3};\n" \
    : "+f"(d[0]), "+f"(d[1]), "+f"(d[2]), "+f"(d[3]) \
    : "r"(a[0]), "r"(a[1]), "r"(a[2]), "r"(a[3]), "r"(b[0]), "r"(b[1]))

#define ASTR 40

// ---------------- init + grammar masks (merged) ----------------
__global__ void k_initw(const int* __restrict__ lhs, const float* __restrict__ ts0,
                        const int* __restrict__ gg) {
    int tb = blockIdx.x;            // 2560 blocks, 64 threads
    int tid = threadIdx.x;
    // mask job
    int t = tb / Bb, b = tb % Bb;
    __shared__ unsigned char ws[Vv];
    __shared__ int f0;
    for (int v = tid; v < Vv; v += 64) ws[v] = 0;
    if (tid == 0) f0 = 0;
    __syncthreads();
    if (tid < OPTo) {
        int base = ((b*OPTo + tid)*4)*SEQs + t;
        int sym = gg[base];
        int m   = gg[base + 3*SEQs];
        if (m) { if (sym > 0) ws[sym] = 1; else f0 = 1; }
    }
    __syncthreads();
    if (tid == 0) ws[0] = (unsigned char)f0;
    __syncthreads();
    unsigned char* outp = d_w + (size_t)tb*Vv;
    for (int v = tid; v < Vv; v += 64) outp[v] = ws[v];
    // init jobs
    if (tb < Bb && tid == 0) d_amax[tb] = 0xFFFFFFFFull - (unsigned)lhs[tb];
    if (tb >= 256 && tb < 256 + 1024) {
        int i = (tb - 256)*64 + tid;
        d_ts[i] = ts0[i];
    }
}

// ---------------- copy small outputs ----------------
__global__ void k_copy(const int* __restrict__ lhs, const int* __restrict__ lmask,
                       const int* __restrict__ gg, float* __restrict__ out) {
    for (int i = blockIdx.x*blockDim.x + threadIdx.x; i < OFF_OPT; i += gridDim.x*blockDim.x) {
        if (i < 256)       out[i] = (float)lhs[i];
        else if (i < 512)  out[i] = (float)lmask[i-256];
        else               out[i] = (float)gg[i-512];
    }
}

// ---------------- fp32 SGEMM (only for gh precompute) ----------------
__global__ void sgemm64(const float* __restrict__ A, const float* __restrict__ Bm,
                        const float* __restrict__ bias, float* __restrict__ C,
                        int M, int N, int K) {
    __shared__ float As[64][17];
    __shared__ float Bs[16][65];
    int tid = threadIdx.x;
    int tx = tid & 15, ty = tid >> 4;
    int m0 = blockIdx.y*64, n0 = blockIdx.x*64;
    float acc[4][4];
    #pragma unroll
    for (int i=0;i<4;i++) {
        #pragma unroll
        for (int j=0;j<4;j++) acc[i][j]=0.f;
    }
    for (int k0 = 0; k0 < K; k0 += 16) {
        #pragma unroll
        for (int i = 0; i < 4; i++) {
            int idx = tid + i*256;
            int r = idx >> 4, c = idx & 15;
            As[r][c] = A[(size_t)(m0+r)*K + k0 + c];
        }
        #pragma unroll
        for (int i = 0; i < 4; i++) {
            int idx = tid + i*256;
            int r = idx >> 6, c = idx & 63;
            Bs[r][c] = Bm[(size_t)(k0+r)*N + n0 + c];
        }
        __syncthreads();
        #pragma unroll
        for (int kk = 0; kk < 16; kk++) {
            float a[4], b[4];
            #pragma unroll
            for (int i=0;i<4;i++) a[i] = As[ty*4+i][kk];
            #pragma unroll
            for (int j=0;j<4;j++) b[j] = Bs[kk][tx*4+j];
            #pragma unroll
            for (int i=0;i<4;i++) {
                #pragma unroll
                for (int j=0;j<4;j++) acc[i][j] += a[i]*b[j];
            }
        }
        __syncthreads();
    }
    #pragma unroll
    for (int i=0;i<4;i++) {
        #pragma unroll
        for (int j=0;j<4;j++)
            C[(size_t)(m0+ty*4+i)*N + n0+tx*4+j] = acc[i][j] + bias[n0+tx*4+j];
    }
}

// ---------------- fused prep: transposes + splits ----------------
// jobs by blockIdx.x:
//  [0,5008):   Wtok^T -> d_WhiT (bf16, 1 term)   313 x 16 tiles
//  [5008,5512): Wsym^T -> d_WsymHiT/LoT          63 x 8 tiles
//  [5512,5704): Wx^T   -> d_WxHiT/LoT            24 x 8 tiles
//  [5704,6204): emb split -> d_embHi/Lo          500 blocks
__global__ void k_prep(const float* __restrict__ Wtok, const float* __restrict__ Wsym,
                       const float* __restrict__ Wx, const float* __restrict__ emb) {
    __shared__ float tile[32][33];
    int bi = blockIdx.x;
    int tid = threadIdx.x;
    int tx = tid & 31, ty = tid >> 5;   // 32 x 8
    if (bi < 5008) {
        int n0 = (bi % 313)*32, k0 = (bi / 313)*32;
        #pragma unroll
        for (int i=0;i<4;i++) {
            int k = k0 + ty + i*8, n = n0 + tx;
            tile[ty+i*8][tx] = (n < VTt) ? Wtok[(size_t)k*VTt + n] : 0.f;
        }
        __syncthreads();
        #pragma unroll
        for (int i=0;i<4;i++) {
            int n = n0 + ty + i*8, k = k0 + tx;
            if (n < VTt)
                d_WhiT[(size_t)n*512 + k] = __float2bfloat16(tile[tx][ty+i*8]);
        }
    } else if (bi < 5512) {
        int idx = bi - 5008;
        int n0 = (idx % 63)*32, k0 = (idx / 63)*32;
        #pragma unroll
        for (int i=0;i<4;i++) {
            int k = k0 + ty + i*8, n = n0 + tx;
            tile[ty+i*8][tx] = (n < Vv) ? Wsym[(size_t)k*Vv + n] : 0.f;
        }
        __syncthreads();
        #pragma unroll
        for (int i=0;i<4;i++) {
            int n = n0 + ty + i*8, k = k0 + tx;
            if (n < Vv) {
                float v = tile[tx][ty+i*8];
                __nv_bfloat16 h = __float2bfloat16(v);
                d_WsymHiT[(size_t)n*Dd + k] = h;
                d_WsymLoT[(size_t)n*Dd + k] = __float2bfloat16(v - __bfloat162float(h));
            }
        }
    } else if (bi < 5704) {
        int idx = bi - 5512;
        int n0 = (idx % 24)*32, k0 = (idx / 24)*32;
        #pragma unroll
        for (int i=0;i<4;i++) {
            int k = k0 + ty + i*8, n = n0 + tx;
            tile[ty+i*8][tx] = Wx[(size_t)k*G3 + n];
        }
        __syncthreads();
        #pragma unroll
        for (int i=0;i<4;i++) {
            int n = n0 + ty + i*8, k = k0 + tx;
            float v = tile[tx][ty+i*8];
            __nv_bfloat16 h = __float2bfloat16(v);
            d_WxHiT[(size_t)n*Dd + k] = h;
            d_WxLoT[(size_t)n*Dd + k] = __float2bfloat16(v - __bfloat162float(h));
        }
    } else {
        int idx = bi - 5704;
        int base = idx*1024 + tid*4;
        #pragma unroll
        for (int q=0;q<4;q++) {
            float v = emb[base+q];
            __nv_bfloat16 h = __float2bfloat16(v);
            d_embHi[base+q] = h;
            d_embLo[base+q] = __float2bfloat16(v - __bfloat162float(h));
        }
    }
}

// ============================================================================
// Persistent kernel: 10-step loop + lse + opts + prepA. grid=NB=148, 256 thr.
// ============================================================================
__global__ __launch_bounds__(256) void k_persist(
    const float* __restrict__ ts0, const float* __restrict__ emb,
    const float* __restrict__ mem,
    const float* __restrict__ bx, const float* __restrict__ Wc,
    const float* __restrict__ bc,
    const float* __restrict__ bsym, const int* __restrict__ gg,
    float* __restrict__ out)
{
    __shared__ __nv_bfloat16 sAh[64*ASTR], sAl[64*ASTR], sBh[64*ASTR], sBl[64*ASTR];
    __shared__ float As[32][17];
    __shared__ float Bs[16][33];
    __shared__ float sGru[Dd + SRCs];
    __shared__ float sVals[OPTo*SEQs];
    __shared__ float sSol[OPTo];
    __shared__ int   sBest;

    const int tid = threadIdx.x;
    const int blk = blockIdx.x;
    const int lane = tid & 31, warp = tid >> 5;
    const int wm = warp >> 2, wn = warp & 3;          // 2x4 warp grid
    const int g = lane >> 2, tq = lane & 3;
    const int ldr = tid >> 2;                          // 0..63
    const int ldc = (tid & 3) * 8;                     // 0,8,16,24
    const float LT = logf(1e-13f);

    for (int t = 0; t < SEQs; t++) {
        // ---------- Phase A (MMA): gx = emb[prev] @ Wx + bx  (64x64 tiles, 4x12)
        for (int tile = blk; tile < 48; tile += NB) {
            int mt = tile / 12, nt = tile % 12;
            int m0 = mt*64, n0 = nt*64;
            float acc[2][2][4];
            #pragma unroll
            for (int i=0;i<2;i++) {
                #pragma unroll
                for (int j=0;j<2;j++) {
                    #pragma unroll
                    for (int q=0;q<4;q++) acc[i][j][q]=0.f;
                }
            }
            unsigned long long pk = d_amax[m0 + ldr];
            int pr = (int)(0xFFFFFFFFu - (unsigned)(pk & 0xFFFFFFFFull));
            for (int k0 = 0; k0 < Dd; k0 += 32) {
                *(uint4*)&sAh[ldr*ASTR + ldc] = *(const uint4*)(d_embHi + (size_t)pr*Dd + k0 + ldc);
                *(uint4*)&sAl[ldr*ASTR + ldc] = *(const uint4*)(d_embLo + (size_t)pr*Dd + k0 + ldc);
                *(uint4*)&sBh[ldr*ASTR + ldc] = *(const uint4*)(d_WxHiT + (size_t)(n0+ldr)*Dd + k0 + ldc);
                *(uint4*)&sBl[ldr*ASTR + ldc] = *(const uint4*)(d_WxLoT + (size_t)(n0+ldr)*Dd + k0 + ldc);
                __syncthreads();
                #pragma unroll
                for (int ks = 0; ks < 2; ks++) {
                    int kb = ks*16 + tq*2;
                    uint32_t ah[2][4], al[2][4], bh[2][2], bl[2][2];
                    #pragma unroll
                    for (int mi=0;mi<2;mi++) {
                        int rb = wm*32 + mi*16;
                        ah[mi][0] = *(const uint32_t*)&sAh[(rb+g)*ASTR + kb];
                        ah[mi][1] = *(const uint32_t*)&sAh[(rb+g+8)*ASTR + kb];
                        ah[mi][2] = *(const uint32_t*)&sAh[(rb+g)*ASTR + kb + 8];
                        ah[mi][3] = *(const uint32_t*)&sAh[(rb+g+8)*ASTR + kb + 8];
                        al[mi][0] = *(const uint32_t*)&sAl[(rb+g)*ASTR + kb];
                        al[mi][1] = *(const uint32_t*)&sAl[(rb+g+8)*ASTR + kb];
                        al[mi][2] = *(const uint32_t*)&sAl[(rb+g)*ASTR + kb + 8];
                        al[mi][3] = *(const uint32_t*)&sAl[(rb+g+8)*ASTR + kb + 8];
                    }
                    #pragma unroll
                    for (int ni=0;ni<2;ni++) {
                        int nb = wn*16 + ni*8 + g;
                        bh[ni][0] = *(const uint32_t*)&sBh[nb*ASTR + kb];
                        bh[ni][1] = *(const uint32_t*)&sBh[nb*ASTR + kb + 8];
                        bl[ni][0] = *(const uint32_t*)&sBl[nb*ASTR + kb];
                        bl[ni][1] = *(const uint32_t*)&sBl[nb*ASTR + kb + 8];
                    }
                    #pragma unroll
                    for (int mi=0;mi<2;mi++) {
                        #pragma unroll
                        for (int ni=0;ni<2;ni++) {
                            MMA16816(acc[mi][ni], ah[mi], bh[ni]);
                            MMA16816(acc[mi][ni], ah[mi], bl[ni]);
                            MMA16816(acc[mi][ni], al[mi], bh[ni]);
                        }
                    }
                }
                __syncthreads();
            }
            #pragma unroll
            for (int mi=0;mi<2;mi++) {
                int r0 = m0 + wm*32 + mi*16 + g;
                #pragma unroll
                for (int ni=0;ni<2;ni++) {
                    int c0 = n0 + wn*16 + ni*8 + tq*2;
                    d_gx[(size_t)r0*G3 + c0]       = acc[mi][ni][0] + bx[c0];
                    d_gx[(size_t)r0*G3 + c0+1]     = acc[mi][ni][1] + bx[c0+1];
                    d_gx[(size_t)(r0+8)*G3 + c0]   = acc[mi][ni][2] + bx[c0];
                    d_gx[(size_t)(r0+8)*G3 + c0+1] = acc[mi][ni][3] + bx[c0+1];
                }
            }
        }
        gsync();

        // ---------- Phase B: GRU + attention + cat; reset amax
        for (int b = blk; b < Bb; b += NB) {
            int j = tid;
            if (j == 0) d_amax[b] = 0ull;
            float xr = d_gx[b*G3 + j], xz = d_gx[b*G3 + Dd + j], xn = d_gx[b*G3 + 2*Dd + j];
            float hr = d_gh[b*G3 + j], hz = d_gh[b*G3 + Dd + j], hn = d_gh[b*G3 + 2*Dd + j];
            float r = 1.f/(1.f + expf(-(xr+hr)));
            float z = 1.f/(1.f + expf(-(xz+hz)));
            float n = tanhf(xn + r*hn);
            float h = (1.f - z)*n + z*ts0[b*Dd + j];
            sGru[j] = h;
            __syncthreads();
            float* att = sGru + Dd;
            for (int s = warp; s < SRCs; s += 8) {
                const float* mrow = mem + ((size_t)b*SRCs + s)*Dd;
                float sum = 0.f;
                for (int k = lane; k < Dd; k += 32) sum += sGru[k]*mrow[k];
                #pragma unroll
                for (int o=16;o;o>>=1) sum += __shfl_down_sync(0xffffffffu, sum, o);
                if (lane == 0) att[s] = sum;
            }
            __syncthreads();
            if (tid == 0) {
                float m = att[0];
                for (int s=1;s<SRCs;s++) m = fmaxf(m, att[s]);
                float ss = 0.f;
                for (int s=0;s<SRCs;s++){ att[s] = expf(att[s]-m); ss += att[s]; }
                float inv = 1.f/ss;
                for (int s=0;s<SRCs;s++) att[s] *= inv;
            }
            __syncthreads();
            float ctx = 0.f;
            for (int s=0;s<SRCs;s++) ctx += att[s]*mem[((size_t)b*SRCs+s)*Dd + j];
            d_cat[b*2*Dd + j]      = ctx;
            d_cat[b*2*Dd + Dd + j] = h;
            __syncthreads();
        }
        gsync();

        // ---------- Phase C (fp32 32x32): soa = tanh(cat@Wc+bc) -> hi/lo; ts update
        for (int tile = blk; tile < 64; tile += NB) {
            int mt = tile >> 3, nt = tile & 7;
            int m0 = mt*32, n0 = nt*32;
            int tx = tid & 15, ty = tid >> 4;
            float acc[2][2];
            acc[0][0]=acc[0][1]=acc[1][0]=acc[1][1]=0.f;
            for (int k0 = 0; k0 < 2*Dd; k0 += 16) {
                {
                    int idx = tid*2;
                    int r = idx >> 4, c = idx & 15;
                    const float* cr = d_cat + (size_t)(m0+r)*2*Dd + k0 + c;
                    As[r][c] = cr[0]; As[r][c+1] = cr[1];
                }
                {
                    int idx = tid*2;
                    int r = idx >> 5, c = idx & 31;
                    const float* wr_ = Wc + (size_t)(k0+r)*Dd + n0 + c;
                    Bs[r][c] = wr_[0]; Bs[r][c+1] = wr_[1];
                }
                __syncthreads();
                #pragma unroll
                for (int kk = 0; kk < 16; kk++) {
                    float a0 = As[ty*2][kk], a1 = As[ty*2+1][kk];
                    float b0 = Bs[kk][tx*2], b1 = Bs[kk][tx*2+1];
                    acc[0][0] += a0*b0; acc[0][1] += a0*b1;
                    acc[1][0] += a1*b0; acc[1][1] += a1*b1;
                }
                __syncthreads();
            }
            #pragma unroll
            for (int i=0;i<2;i++) {
                int tx2 = tid & 15, ty2 = tid >> 4;
                #pragma unroll
                for (int j=0;j<2;j++) {
                    int r = m0+ty2*2+i, c = n0+tx2*2+j;
                    float s = tanhf(acc[i][j] + bc[c]);
                    __nv_bfloat16 h = __float2bfloat16(s);
                    d_soaHi[(size_t)r*Dd + c] = h;
                    d_soaLo[(size_t)r*Dd + c] = __float2bfloat16(s - __bfloat162float(h));
                    d_ts[(size_t)r*Dd + c] = tanhf(d_ts[(size_t)r*Dd + c] + s);
                }
            }
        }
        gsync();

        // ---------- Phase D (MMA): clog = soa @ Wsym + bsym + mask; argmax
        for (int tile = blk; tile < 128; tile += NB) {
            int mt = tile >> 5, nt = tile & 31;   // 4 x 32
            int m0 = mt*64, n0 = nt*64;
            float acc[2][2][4];
            #pragma unroll
            for (int i=0;i<2;i++) {
                #pragma unroll
                for (int j=0;j<2;j++) {
                    #pragma unroll
                    for (int q=0;q<4;q++) acc[i][j][q]=0.f;
                }
            }
            int nr = n0 + ldr;
            const bool nok = (nr < Vv);
            for (int k0 = 0; k0 < Dd; k0 += 32) {
                *(uint4*)&sAh[ldr*ASTR + ldc] = *(const uint4*)(d_soaHi + (size_t)(m0+ldr)*Dd + k0 + ldc);
                *(uint4*)&sAl[ldr*ASTR + ldc] = *(const uint4*)(d_soaLo + (size_t)(m0+ldr)*Dd + k0 + ldc);
                uint4 vh = make_uint4(0,0,0,0), vl = make_uint4(0,0,0,0);
                if (nok) {
                    vh = *(const uint4*)(d_WsymHiT + (size_t)nr*Dd + k0 + ldc);
                    vl = *(const uint4*)(d_WsymLoT + (size_t)nr*Dd + k0 + ldc);
                }
                *(uint4*)&sBh[ldr*ASTR + ldc] = vh;
                *(uint4*)&sBl[ldr*ASTR + ldc] = vl;
                __syncthreads();
                #pragma unroll
                for (int ks = 0; ks < 2; ks++) {
                    int kb = ks*16 + tq*2;
                    uint32_t ah[2][4], al[2][4], bh[2][2], bl[2][2];
                    #pragma unroll
                    for (int mi=0;mi<2;mi++) {
                        int rb = wm*32 + mi*16;
                        ah[mi][0] = *(const uint32_t*)&sAh[(rb+g)*ASTR + kb];
                        ah[mi][1] = *(const uint32_t*)&sAh[(rb+g+8)*ASTR + kb];
                        ah[mi][2] = *(const uint32_t*)&sAh[(rb+g)*ASTR + kb + 8];
                        ah[mi][3] = *(const uint32_t*)&sAh[(rb+g+8)*ASTR + kb + 8];
                        al[mi][0] = *(const uint32_t*)&sAl[(rb+g)*ASTR + kb];
                        al[mi][1] = *(const uint32_t*)&sAl[(rb+g+8)*ASTR + kb];
                        al[mi][2] = *(const uint32_t*)&sAl[(rb+g)*ASTR + kb + 8];
                        al[mi][3] = *(const uint32_t*)&sAl[(rb+g+8)*ASTR + kb + 8];
                    }
                    #pragma unroll
                    for (int ni=0;ni<2;ni++) {
                        int nb = wn*16 + ni*8 + g;
                        bh[ni][0] = *(const uint32_t*)&sBh[nb*ASTR + kb];
                        bh[ni][1] = *(const uint32_t*)&sBh[nb*ASTR + kb + 8];
                        bl[ni][0] = *(const uint32_t*)&sBl[nb*ASTR + kb];
                        bl[ni][1] = *(const uint32_t*)&sBl[nb*ASTR + kb + 8];
                    }
                    #pragma unroll
                    for (int mi=0;mi<2;mi++) {
                        #pragma unroll
                        for (int ni=0;ni<2;ni++) {
                            MMA16816(acc[mi][ni], ah[mi], bh[ni]);
                            MMA16816(acc[mi][ni], ah[mi], bl[ni]);
                            MMA16816(acc[mi][ni], al[mi], bh[ni]);
                        }
                    }
                }
                __syncthreads();
            }
            // epilogue: bias + mask + store + argmax (shfl over tq, then atomic)
            #pragma unroll
            for (int mi=0;mi<2;mi++) {
                int rA = m0 + wm*32 + mi*16 + g;
                int rB = rA + 8;
                const unsigned char* wA = d_w + ((size_t)t*Bb + rA)*Vv;
                const unsigned char* wB = d_w + ((size_t)t*Bb + rB)*Vv;
                float* cA = d_clog + ((size_t)t*Bb + rA)*Vv;
                float* cB = d_clog + ((size_t)t*Bb + rB)*Vv;
                unsigned long long bestA = 0ull, bestB = 0ull;
                #pragma unroll
                for (int ni=0;ni<2;ni++) {
                    int c0 = n0 + wn*16 + ni*8 + tq*2;
                    #pragma unroll
                    for (int q=0;q<2;q++) {
                        int c = c0 + q;
                        if (c < Vv) {
                            float bsv = bsym[c];
                            float vA = acc[mi][ni][q]   + bsv; if (!wA[c]) vA += LT;
                            float vB = acc[mi][ni][2+q] + bsv; if (!wB[c]) vB += LT;
                            cA[c] = vA; cB[c] = vB;
                            unsigned long long kA = ((unsigned long long)f2mono(vA) << 32) | (0xFFFFFFFFu - (unsigned)c);
                            unsigned long long kB = ((unsigned long long)f2mono(vB) << 32) | (0xFFFFFFFFu - (unsigned)c);
                            if (kA > bestA) bestA = kA;
                            if (kB > bestB) bestB = kB;
                        }
                    }
                }
                #pragma unroll
                for (int o=1;o<4;o<<=1) {
                    unsigned long long oA = __shfl_xor_sync(0xffffffffu, bestA, o);
                    unsigned long long oB = __shfl_xor_sync(0xffffffffu, bestB, o);
                    if (oA > bestA) bestA = oA;
                    if (oB > bestB) bestB = oB;
                }
                if (tq == 0) {
                    if (bestA) atomicMax(&d_amax[rA], bestA);
                    if (bestB) atomicMax(&d_amax[rB], bestB);
                }
            }
        }
        gsync();
    }

    // ---------- Phase L: logsumexp per (t,b), warp per row
    for (int tb = blk*8 + warp; tb < SEQs*Bb; tb += NB*8) {
        const float* row = d_clog + (size_t)tb*Vv;
        float m = -1e30f;
        for (int v = lane; v < Vv; v += 32) m = fmaxf(m, row[v]);
        #pragma unroll
        for (int o=16;o;o>>=1) m = fmaxf(m, __shfl_xor_sync(0xffffffffu, m, o));
        float s = 0.f;
        for (int v = lane; v < Vv; v += 32) s += expf(row[v]-m);
        #pragma unroll
        for (int o=16;o;o>>=1) s += __shfl_xor_sync(0xffffffffu, s, o);
        if (lane == 0) d_lse[tb] = m + logf(s);
    }
    gsync();

    // ---------- Phase O: opts_logp, best, topo
    for (int b = blk; b < Bb; b += NB) {
        if (tid < OPTo*SEQs) {
            int o = tid / SEQs, t = tid % SEQs;
            int base = ((b*OPTo + o)*4)*SEQs + t;
            int m = gg[base + 3*SEQs];
            float v = 0.f;
            if (m) {
                int sym = gg[base];
                v = logf(expf(d_clog[((size_t)t*Bb + b)*Vv + sym] - d_lse[t*Bb + b]) + 1e-13f);
            }
            sVals[tid] = v;
        }
        __syncthreads();
        if (tid < OPTo) {
            float s = 0.f;
            #pragma unroll
            for (int t=0;t<SEQs;t++) s += sVals[tid*SEQs + t];
            sSol[tid] = s;
            out[OFF_OPT + b*OPTo + tid] = s;
        }
        __syncthreads();
        if (tid == 0) {
            int bi = 0; float bv = sSol[0];
            for (int o=1;o<OPTo;o++) if (sSol[o] > bv) { bv = sSol[o]; bi = o; }
            sBest = bi;
        }
        __syncthreads();
        if (tid < 4*SEQs) {
            int c = tid / SEQs, s = tid % SEQs;
            int val = gg[((b*OPTo + sBest)*4 + c)*SEQs + s];
            out[OFF_TOPO + c*(Bb*SEQs) + b*SEQs + s] = (float)val;
            if (c == 0) d_sym[b*SEQs + s] = val;
        }
        __syncthreads();
    }
    gsync();

    // ---------- Phase P: prep A rows (bf16)
    for (int idx = blk*256 + tid; idx < Bb*SEQs*512; idx += NB*256) {
        int r = idx >> 9, k = idx & 511;
        int b = r / SEQs;
        float v = (k < Dd) ? emb[(size_t)d_sym[r]*Dd + k] : d_ts[b*Dd + (k - Dd)];
        d_Ahi[idx] = __float2bfloat16(v);
    }
}

// ---------------- exact_logit GEMM: single bf16 mma, 128x128x32, double-buffered --
#define XSTR 40

__global__ __launch_bounds__(256) void k_exact(const float* __restrict__ btok,
                                               const float* __restrict__ tok,
                                               float* __restrict__ out) {
    __shared__ __nv_bfloat16 sA[2][128*XSTR], sB[2][128*XSTR];
    int tid = threadIdx.x;
    int m0 = blockIdx.y*128, n0 = blockIdx.x*128;
    int lane = tid & 31, warp = tid >> 5;
    int wm = warp >> 2, wn = warp & 3;
    int g = lane >> 2, tq = lane & 3;
    float acc[4][4][4];
    #pragma unroll
    for (int i=0;i<4;i++) {
        #pragma unroll
        for (int j=0;j<4;j++) {
            #pragma unroll
            for (int q=0;q<4;q++) acc[i][j][q] = 0.f;
        }
    }

    int row = tid >> 1;
    int kh  = (tid & 1) << 4;
    int nr  = n0 + row;
    const bool nok = (nr < VTt);

    uint4 ra0, ra1, rb0, rb1;
    const uint4 z0 = make_uint4(0,0,0,0);

    {
        const uint4* p = (const uint4*)(d_Ahi + (size_t)(m0+row)*512 + kh);
        ra0 = p[0]; ra1 = p[1];
        rb0 = z0; rb1 = z0;
        if (nok) {
            const uint4* q = (const uint4*)(d_WhiT + (size_t)nr*512 + kh);
            rb0 = q[0]; rb1 = q[1];
        }
    }
    *(uint4*)&sA[0][row*XSTR + kh]     = ra0;
    *(uint4*)&sA[0][row*XSTR + kh + 8] = ra1;
    *(uint4*)&sB[0][row*XSTR + kh]     = rb0;
    *(uint4*)&sB[0][row*XSTR + kh + 8] = rb1;
    __syncthreads();

    int buf = 0;
    for (int k0 = 0; k0 < 512; k0 += 32) {
        int nxt = k0 + 32;
        if (nxt < 512) {
            const uint4* p = (const uint4*)(d_Ahi + (size_t)(m0+row)*512 + nxt + kh);
            ra0 = p[0]; ra1 = p[1];
            rb0 = z0; rb1 = z0;
            if (nok) {
                const uint4* q = (const uint4*)(d_WhiT + (size_t)nr*512 + nxt + kh);
                rb0 = q[0]; rb1 = q[1];
            }
        }
        const __nv_bfloat16* cA = sA[buf];
        const __nv_bfloat16* cB = sB[buf];
        #pragma unroll
        for (int ks = 0; ks < 2; ks++) {
            int kb = ks*16;
            uint32_t ah[4][4];
            #pragma unroll
            for (int mi=0;mi<4;mi++) {
                int rb = wm*64 + mi*16;
                int c0 = kb + tq*2;
                ah[mi][0] = *(const uint32_t*)&cA[(rb+g)*XSTR + c0];
                ah[mi][1] = *(const uint32_t*)&cA[(rb+g+8)*XSTR + c0];
                ah[mi][2] = *(const uint32_t*)&cA[(rb+g)*XSTR + c0 + 8];
                ah[mi][3] = *(const uint32_t*)&cA[(rb+g+8)*XSTR + c0 + 8];
            }
            uint32_t bh[4][2];
            #pragma unroll
            for (int ni=0;ni<4;ni++) {
                int nb = wn*32 + ni*8 + g;
                bh[ni][0] = *(const uint32_t*)&cB[nb*XSTR + kb + tq*2];
                bh[ni][1] = *(const uint32_t*)&cB[nb*XSTR + kb + tq*2 + 8];
            }
            #pragma unroll
            for (int mi=0;mi<4;mi++) {
                #pragma unroll
                for (int ni=0;ni<4;ni++) {
                    MMA16816(acc[mi][ni], ah[mi], bh[ni]);
                }
            }
        }
        if (nxt < 512) {
            *(uint4*)&sA[buf^1][row*XSTR + kh]     = ra0;
            *(uint4*)&sA[buf^1][row*XSTR + kh + 8] = ra1;
            *(uint4*)&sB[buf^1][row*XSTR + kh]     = rb0;
            *(uint4*)&sB[buf^1][row*XSTR + kh + 8] = rb1;
            __syncthreads();
            buf ^= 1;
        }
    }

    const float LT = logf(1e-13f);
    #pragma unroll
    for (int mi=0;mi<4;mi++) {
        int r0 = m0 + wm*64 + mi*16 + g;
        int s0 = d_sym[r0];
        int s1 = d_sym[r0 + 8];
        #pragma unroll
        for (int ni=0;ni<4;ni++) {
            int c0 = n0 + wn*32 + ni*8 + tq*2;
            if (c0 < VTt) {
                float b0 = btok[c0];
                out[OFF_EX + (size_t)r0*VTt + c0]     = acc[mi][ni][0] + b0 + (tok[(size_t)s0*VTt + c0] > 0.f ? 0.f : LT);
                out[OFF_EX + (size_t)(r0+8)*VTt + c0] = acc[mi][ni][2] + b0 + (tok[(size_t)s1*VTt + c0] > 0.f ? 0.f : LT);
            }
            if (c0 + 1 < VTt) {
                float b1 = btok[c0+1];
                out[OFF_EX + (size_t)r0*VTt + c0+1]     = acc[mi][ni][1] + b1 + (tok[(size_t)s0*VTt + c0+1] > 0.f ? 0.f : LT);
                out[OFF_EX + (size_t)(r0+8)*VTt + c0+1] = acc[mi][ni][3] + b1 + (tok[(size_t)s1*VTt + c0+1] > 0.f ? 0.f : LT);
            }
        }
    }
}

// ---------------- host launcher ----------------
extern "C" void kernel_launch(void* const* d_in, const int* in_sizes, int n_in,
                              void* d_out, int out_size) {
    const int*   lhs   = (const int*)d_in[0];
    const int*   lmask = (const int*)d_in[1];
    const float* ts0   = (const float*)d_in[2];
    const int*   gg    = (const int*)d_in[3];
    const float* emb   = (const float*)d_in[4];
    const float* mem   = (const float*)d_in[5];
    const float* Wx    = (const float*)d_in[6];
    const float* Wh    = (const float*)d_in[7];
    const float* bx    = (const float*)d_in[8];
    const float* bh    = (const float*)d_in[9];
    const float* Wc    = (const float*)d_in[10];
    const float* bc    = (const float*)d_in[11];
    const float* Wsym  = (const float*)d_in[12];
    const float* bsym  = (const float*)d_in[13];
    const float* Wtok  = (const float*)d_in[14];
    const float* btok  = (const float*)d_in[15];
    const float* tok   = (const float*)d_in[16];
    float* out = (float*)d_out;

    void* pv;
    cudaGetSymbolAddress(&pv, d_gh);   float* p_gh = (float*)pv;

    k_initw<<<SEQs*Bb, 64>>>(lhs, ts0, gg);
    sgemm64<<<dim3(12,4), 256>>>(ts0, Wh, bh, p_gh, Bb, G3, Dd);   // gh constant
    k_prep<<<6204, 256>>>(Wtok, Wsym, Wx, emb);
    k_persist<<<NB, 256>>>(ts0, emb, mem, bx, Wc, bc, bsym, gg, out);
    k_copy<<<642, 256>>>(lhs, lmask, gg, out);
    k_exact<<<dim3((VTt+127)/128, (Bb*SEQs)/128), 256>>>(btok, tok, out);
}